// round 9
// baseline (speedup 1.0000x reference)
#include <cuda_runtime.h>
#include <cuda_fp16.h>
#include <cstdint>
#include <cstddef>

#define DD 256
#define PP 512
#define TT 65536
#define LSEQ 2048
#define EPSL 1e-5f

__device__ __half g_wcat[DD * 768];
__device__ __half g_wq[512 * DD];
__device__ __half g_wo[DD * 512];
__device__ __half g_xh[(size_t)TT * DD];     // half(x)
__device__ __half g_xln[(size_t)TT * DD];    // conv+LN
__device__ __half g_q[(size_t)TT * 512];
__device__ __half g_att[(size_t)TT * 512];
__device__ __half g_k[8 * PP * 64];          // [h][w][d], scaled 1/8
__device__ __half g_vT[8 * 64 * PP];         // [h][d][w]

__device__ __forceinline__ uint32_t s2u(const void* p) {
    uint32_t a;
    asm("{ .reg .u64 t; cvta.to.shared.u64 t, %1; cvt.u32.u64 %0, t; }" : "=r"(a) : "l"(p));
    return a;
}
__device__ __forceinline__ void mma16(float* c, const uint32_t* a, uint32_t b0, uint32_t b1) {
    asm volatile(
        "mma.sync.aligned.m16n8k16.row.col.f32.f16.f16.f32 "
        "{%0,%1,%2,%3}, {%4,%5,%6,%7}, {%8,%9}, {%0,%1,%2,%3};"
        : "+f"(c[0]), "+f"(c[1]), "+f"(c[2]), "+f"(c[3])
        : "r"(a[0]), "r"(a[1]), "r"(a[2]), "r"(a[3]), "r"(b0), "r"(b1));
}
__device__ __forceinline__ void ldsm4(uint32_t* r, uint32_t addr) {
    asm volatile("ldmatrix.sync.aligned.m8n8.x4.shared.b16 {%0,%1,%2,%3}, [%4];"
        : "=r"(r[0]), "=r"(r[1]), "=r"(r[2]), "=r"(r[3]) : "r"(addr));
}
__device__ __forceinline__ void cpa16(uint32_t dst, const __half* src) {
    asm volatile("cp.async.ca.shared.global [%0], [%1], 16;" :: "r"(dst), "l"(src));
}
__device__ __forceinline__ void cpa16p(uint32_t dst, const __half* src, int ok) {
    int sz = ok ? 16 : 0;
    asm volatile("cp.async.ca.shared.global [%0], [%1], 16, %2;" :: "r"(dst), "l"(src), "r"(sz));
}
#define CPCOMMIT() asm volatile("cp.async.commit_group;" ::: "memory")

// ---------- K0: weight prep ----------
__global__ void __launch_bounds__(256) k_prep(const float* __restrict__ conv_w,
                                              const float* __restrict__ wq,
                                              const float* __restrict__ wout) {
    int idx = blockIdx.x * 256 + threadIdx.x;
    if (idx < DD * 768) {
        int o = idx / 768, col = idx % 768;
        g_wcat[idx] = __float2half_rn(conv_w[o * 768 + (col & 255) * 3 + (col >> 8)]);
    }
    if (idx < 512 * DD) g_wq[idx] = __float2half_rn(wq[idx]);
    if (idx < DD * 512) g_wo[idx] = __float2half_rn(wout[idx]);
}

// ---------- K0b: x -> half ----------
__global__ void __launch_bounds__(256) k_prepx(const float* __restrict__ x) {
    size_t i = ((size_t)blockIdx.x * 256 + threadIdx.x) * 8;
    float4 v0 = *(const float4*)(x + i);
    float4 v1 = *(const float4*)(x + i + 4);
    half2 h[4];
    h[0] = __floats2half2_rn(v0.x, v0.y);
    h[1] = __floats2half2_rn(v0.z, v0.w);
    h[2] = __floats2half2_rn(v1.x, v1.y);
    h[3] = __floats2half2_rn(v1.z, v1.w);
    *(uint4*)(g_xh + i) = *(uint4*)h;
}

__device__ __forceinline__ float2 bsum2(float a, float b, float* red) {
    #pragma unroll
    for (int o = 16; o; o >>= 1) {
        a += __shfl_xor_sync(0xffffffffu, a, o);
        b += __shfl_xor_sync(0xffffffffu, b, o);
    }
    __syncthreads();
    if ((threadIdx.x & 31) == 0) {
        red[threadIdx.x >> 5] = a;
        red[(threadIdx.x >> 5) + 8] = b;
    }
    __syncthreads();
    a = 0.f; b = 0.f;
    #pragma unroll
    for (int k = 0; k < 8; k++) { a += red[k]; b += red[k + 8]; }
    return make_float2(a, b);
}

// ---------- K1: pattern double-LN + kv ----------
__global__ void __launch_bounds__(256) k_patkv(const float* __restrict__ pattern,
                                               const float* __restrict__ wkv) {
    __shared__ float sp[8][DD];
    __shared__ float red[16];
    int r0 = blockIdx.x * 8, tid = threadIdx.x;
    for (int r = 0; r < 8; r++) {
        float v = pattern[(size_t)(r0 + r) * DD + tid];
        for (int it = 0; it < 2; it++) {
            float2 s = bsum2(v, v * v, red);
            float mu = s.x * (1.f / DD);
            v = (v - mu) * rsqrtf(s.y * (1.f / DD) - mu * mu + EPSL);
        }
        sp[r][tid] = v;
    }
    __syncthreads();
    for (int m = 0; m < 4; m++) {
        int j = m * 256 + tid;
        float acc[8];
        #pragma unroll
        for (int r = 0; r < 8; r++) acc[r] = 0.f;
        const float* wr = wkv + (size_t)j * DD;
        for (int i = 0; i < DD; i++) {
            float w = wr[i];
            #pragma unroll
            for (int r = 0; r < 8; r++) acc[r] += w * sp[r][i];
        }
        int h = j >> 7, e = j & 127;
        if (e < 64) {
            #pragma unroll
            for (int r = 0; r < 8; r++)
                g_k[((size_t)h * PP + r0 + r) * 64 + e] = __float2half_rn(0.125f * acc[r]);
        } else {
            #pragma unroll
            for (int r = 0; r < 8; r++)
                g_vT[((size_t)h * 64 + e - 64) * PP + r0 + r] = __float2half_rn(acc[r]);
        }
    }
}

// ---------- prefetch one K-chunk (32 halves) ----------
__device__ __forceinline__ void gemm_prefetch(const __half* A, const __half* B,
                                              uint32_t as_u, uint32_t bs_u,
                                              int c, int K, int t0, int n0,
                                              int seq0, int mode, int tid) {
    int b = c & 1, kc = c * 32;
    uint32_t ad = as_u + b * 128 * 40 * 2;
    uint32_t bd = bs_u + b * 256 * 40 * 2;
    if (mode == 0) {
        for (int i = tid; i < 512; i += 512) {
            int r = i >> 2, cc = i & 3;
            int t = t0 + r + (kc >> 8) - 2;
            int ok = t >= seq0;
            const __half* s = A + (size_t)(ok ? t : seq0) * 256 + (kc & 255) + cc * 8;
            cpa16p(ad + (r * 40 + cc * 8) * 2, s, ok);
        }
    } else {
        for (int i = tid; i < 512; i += 512) {
            int r = i >> 2, cc = i & 3;
            cpa16(ad + (r * 40 + cc * 8) * 2, A + (size_t)(t0 + r) * K + kc + cc * 8);
        }
    }
    for (int i = tid; i < 1024; i += 512) {
        int r = i >> 2, cc = i & 3;
        cpa16(bd + (r * 40 + cc * 8) * 2, B + (size_t)(n0 + r) * K + kc + cc * 8);
    }
    CPCOMMIT();
}

// ---------- fused fp16 GEMM: C[128 x 256] = A[128,K] @ B[256,K]^T (+ epilogues) ----------
// mode 0: conv (+cbias +x residual +leaky +LN -> g_xln half)
// mode 1: q (plain -> half)
// mode 2: out (+bout +LN -> out float)
__global__ void __launch_bounds__(512, 1) k_gemm(const __half* __restrict__ A,
                                                 const __half* __restrict__ B,
                                                 const float* __restrict__ x,
                                                 const float* __restrict__ bias,
                                                 void* __restrict__ Cv,
                                                 int K, int ldc, int mode) {
    extern __shared__ __half sm[];
    __half* As = sm;                        // [2][128][40]
    __half* Bs = sm + 2 * 128 * 40;         // [2][256][40]
    __shared__ float sred[128], sqred[128];
    int tid = threadIdx.x, lane = tid & 31, warp = tid >> 5;
    int l16 = lane & 15, lh = lane >> 4;
    int qr = lane >> 2, qc = lane & 3;
    int wm = warp >> 2, wn = warp & 3;
    int t0 = blockIdx.x * 128, n0 = blockIdx.y * 256;
    int seq0 = t0 & ~(LSEQ - 1);
    int NC = K >> 5;

    uint32_t as_u = s2u(As), bs_u = s2u(Bs);
    uint32_t a_frag = as_u + ((wm * 32 + l16) * 40 + lh * 8) * 2;
    uint32_t b_frag = bs_u + ((wn * 64 + l16) * 40 + lh * 8) * 2;

    float cacc[2][8][4];
    #pragma unroll
    for (int mt = 0; mt < 2; mt++)
        #pragma unroll
        for (int nt = 0; nt < 8; nt++)
            #pragma unroll
            for (int i = 0; i < 4; i++) cacc[mt][nt][i] = 0.f;

    gemm_prefetch(A, B, as_u, bs_u, 0, K, t0, n0, seq0, mode, tid);
    for (int c = 0; c < NC; c++) {
        if (c + 1 < NC) {
            gemm_prefetch(A, B, as_u, bs_u, c + 1, K, t0, n0, seq0, mode, tid);
            asm volatile("cp.async.wait_group 1;" ::: "memory");
        } else {
            asm volatile("cp.async.wait_group 0;" ::: "memory");
        }
        __syncthreads();
        int b = c & 1;
        uint32_t af = a_frag + b * 128 * 40 * 2;
        uint32_t bf = b_frag + b * 256 * 40 * 2;
        #pragma unroll
        for (int ks = 0; ks < 2; ks++) {
            uint32_t a0[4], a1[4], bb[4][4];
            ldsm4(a0, af + ks * 32);
            ldsm4(a1, af + 16 * 40 * 2 + ks * 32);
            #pragma unroll
            for (int n2 = 0; n2 < 4; n2++) ldsm4(bb[n2], bf + n2 * 16 * 40 * 2 + ks * 32);
            #pragma unroll
            for (int n2 = 0; n2 < 4; n2++) {
                mma16(cacc[0][n2 * 2],     a0, bb[n2][0], bb[n2][2]);
                mma16(cacc[0][n2 * 2 + 1], a0, bb[n2][1], bb[n2][3]);
                mma16(cacc[1][n2 * 2],     a1, bb[n2][0], bb[n2][2]);
                mma16(cacc[1][n2 * 2 + 1], a1, bb[n2][1], bb[n2][3]);
            }
        }
        __syncthreads();
    }

    if (mode == 1) {
        __half* C = (__half*)Cv;
        #pragma unroll
        for (int mt = 0; mt < 2; mt++)
            #pragma unroll
            for (int nt = 0; nt < 8; nt++) {
                int r = t0 + wm * 32 + mt * 16 + qr;
                int col = n0 + wn * 64 + nt * 8 + qc * 2;
                *(half2*)(C + (size_t)r * ldc + col) =
                    __floats2half2_rn(cacc[mt][nt][0], cacc[mt][nt][1]);
                *(half2*)(C + (size_t)(r + 8) * ldc + col) =
                    __floats2half2_rn(cacc[mt][nt][2], cacc[mt][nt][3]);
            }
        return;
    }

    if (tid < 128) { sred[tid] = 0.f; sqred[tid] = 0.f; }
    __syncthreads();

    float bcol[8][2];
    #pragma unroll
    for (int nt = 0; nt < 8; nt++) {
        float2 b2 = *(const float2*)(bias + wn * 64 + nt * 8 + qc * 2);
        bcol[nt][0] = b2.x; bcol[nt][1] = b2.y;
    }
    float s1[4] = {0.f, 0.f, 0.f, 0.f}, sq[4] = {0.f, 0.f, 0.f, 0.f};
    #pragma unroll
    for (int mt = 0; mt < 2; mt++)
        #pragma unroll
        for (int h2 = 0; h2 < 2; h2++) {
            int rr = mt * 2 + h2;
            int r = wm * 32 + mt * 16 + h2 * 8 + qr;
            #pragma unroll
            for (int nt = 0; nt < 8; nt++) {
                float y0 = cacc[mt][nt][h2 * 2] + bcol[nt][0];
                float y1 = cacc[mt][nt][h2 * 2 + 1] + bcol[nt][1];
                if (mode == 0) {
                    float2 rx = *(const float2*)(x + (size_t)(t0 + r) * 256 +
                                                 wn * 64 + nt * 8 + qc * 2);
                    y0 += rx.x; y1 += rx.y;
                    y0 = y0 > 0.f ? y0 : 0.01f * y0;
                    y1 = y1 > 0.f ? y1 : 0.01f * y1;
                }
                cacc[mt][nt][h2 * 2] = y0;
                cacc[mt][nt][h2 * 2 + 1] = y1;
                s1[rr] += y0 + y1;
                sq[rr] += y0 * y0 + y1 * y1;
            }
        }
    #pragma unroll
    for (int o = 1; o <= 2; o <<= 1)
        #pragma unroll
        for (int rr = 0; rr < 4; rr++) {
            s1[rr] += __shfl_xor_sync(0xffffffffu, s1[rr], o);
            sq[rr] += __shfl_xor_sync(0xffffffffu, sq[rr], o);
        }
    if (qc == 0) {
        #pragma unroll
        for (int rr = 0; rr < 4; rr++) {
            int r = wm * 32 + (rr >> 1) * 16 + (rr & 1) * 8 + qr;
            atomicAdd(&sred[r], s1[rr]);
            atomicAdd(&sqred[r], sq[rr]);
        }
    }
    __syncthreads();
    #pragma unroll
    for (int mt = 0; mt < 2; mt++)
        #pragma unroll
        for (int h2 = 0; h2 < 2; h2++) {
            int r = wm * 32 + mt * 16 + h2 * 8 + qr;
            float mu = sred[r] * (1.f / DD);
            float inv = rsqrtf(sqred[r] * (1.f / DD) - mu * mu + EPSL);
            #pragma unroll
            for (int nt = 0; nt < 8; nt++) {
                int col = wn * 64 + nt * 8 + qc * 2;
                float y0 = (cacc[mt][nt][h2 * 2] - mu) * inv;
                float y1 = (cacc[mt][nt][h2 * 2 + 1] - mu) * inv;
                if (mode == 0) {
                    *(half2*)((__half*)Cv + (size_t)(t0 + r) * ldc + col) =
                        __floats2half2_rn(y0, y1);
                } else {
                    *(float2*)((float*)Cv + (size_t)(t0 + r) * ldc + col) =
                        make_float2(y0, y1);
                }
            }
        }
}

// ---------- fused attention per (128 rows, head), fp16, 256 threads ----------
__global__ void __launch_bounds__(256) k_attn() {
    extern __shared__ __half smh[];
    __half* Aq = smh;                  // [128][72]
    __half* Bk = Aq + 128 * 72;        // [128][72]
    __half* P  = Bk + 128 * 72;        // [128][136]
    __half* Bv = P + 128 * 136;        // [64][136]
    float* rs = (float*)(Bv + 64 * 136);  // [128]
    int tid = threadIdx.x, lane = tid & 31, warp = tid >> 5;
    int l16 = lane & 15, lh = lane >> 4;
    int qr = lane >> 2, qc = lane & 3;
    int wm = warp >> 1, wn = warp & 1;
    int t0 = blockIdx.x * 128, h = blockIdx.y;

    for (int i = tid; i < 1024; i += 256) {
        int r = i >> 3, cc = i & 7;
        *(uint4*)(Aq + r * 72 + cc * 8) =
            *(const uint4*)(g_q + (size_t)(t0 + r) * 512 + h * 64 + cc * 8);
    }
    if (tid < 128) rs[tid] = 0.f;

    uint32_t sqa = s2u(Aq) + ((wm * 32 + l16) * 72 + lh * 8) * 2;
    uint32_t sqb = s2u(Bk) + ((wn * 64 + l16) * 72 + lh * 8) * 2;
    uint32_t spa = s2u(P)  + ((wm * 32 + l16) * 136 + lh * 8) * 2;
    uint32_t spb = s2u(Bv) + ((wn * 32 + l16) * 136 + lh * 8) * 2;

    float oacc[2][4][4];
    #pragma unroll
    for (int mt = 0; mt < 2; mt++)
        #pragma unroll
        for (int nt = 0; nt < 4; nt++)
            #pragma unroll
            for (int i = 0; i < 4; i++) oacc[mt][nt][i] = 0.f;

    for (int c = 0; c < 4; c++) {
        __syncthreads();
        for (int i = tid; i < 1024; i += 256) {
            int r = i >> 3, cc = i & 7;
            *(uint4*)(Bk + r * 72 + cc * 8) =
                *(const uint4*)(g_k + ((size_t)h * PP + c * 128 + r) * 64 + cc * 8);
        }
        for (int i = tid; i < 1024; i += 256) {
            int r = i >> 4, cc = i & 15;
            *(uint4*)(Bv + r * 136 + cc * 8) =
                *(const uint4*)(g_vT + ((size_t)h * 64 + r) * PP + c * 128 + cc * 8);
        }
        __syncthreads();

        // S = q @ k^T  (K = 64 -> 4 k16 steps)
        float s[2][8][4];
        #pragma unroll
        for (int mt = 0; mt < 2; mt++)
            #pragma unroll
            for (int nt = 0; nt < 8; nt++)
                #pragma unroll
                for (int i = 0; i < 4; i++) s[mt][nt][i] = 0.f;
        #pragma unroll
        for (int ks = 0; ks < 4; ks++) {
            uint32_t a0[4], a1[4], b0[4], b1[4], b2[4], b3[4];
            ldsm4(a0, sqa + ks * 32);
            ldsm4(a1, sqa + 16 * 72 * 2 + ks * 32);
            ldsm4(b0, sqb + ks * 32);
            ldsm4(b1, sqb + 16 * 72 * 2 + ks * 32);
            ldsm4(b2, sqb + 32 * 72 * 2 + ks * 32);
            ldsm4(b3, sqb + 48 * 72 * 2 + ks * 32);
            mma16(s[0][0], a0, b0[0], b0[2]); mma16(s[0][1], a0, b0[1], b0[3]);
            mma16(s[0][2], a0, b1[0], b1[2]); mma16(s[0][3], a0, b1[1], b1[3]);
            mma16(s[0][4], a0, b2[0], b2[2]); mma16(s[0][5], a0, b2[1], b2[3]);
            mma16(s[0][6], a0, b3[0], b3[2]); mma16(s[0][7], a0, b3[1], b3[3]);
            mma16(s[1][0], a1, b0[0], b0[2]); mma16(s[1][1], a1, b0[1], b0[3]);
            mma16(s[1][2], a1, b1[0], b1[2]); mma16(s[1][3], a1, b1[1], b1[3]);
            mma16(s[1][4], a1, b2[0], b2[2]); mma16(s[1][5], a1, b2[1], b2[3]);
            mma16(s[1][6], a1, b3[0], b3[2]); mma16(s[1][7], a1, b3[1], b3[3]);
        }

        // exp + rowsum + store P (half)
        #pragma unroll
        for (int mt = 0; mt < 2; mt++) {
            int r = wm * 32 + mt * 16 + qr;
            float sum0 = 0.f, sum1 = 0.f;
            #pragma unroll
            for (int nt = 0; nt < 8; nt++) {
                float e0 = __expf(s[mt][nt][0]);
                float e1 = __expf(s[mt][nt][1]);
                float e2 = __expf(s[mt][nt][2]);
                float e3 = __expf(s[mt][nt][3]);
                sum0 += e0 + e1;
                sum1 += e2 + e3;
                int col = wn * 64 + nt * 8 + qc * 2;
                *(half2*)(P + r * 136 + col) = __floats2half2_rn(e0, e1);
                *(half2*)(P + (r + 8) * 136 + col) = __floats2half2_rn(e2, e3);
            }
            sum0 += __shfl_xor_sync(0xffffffffu, sum0, 1);
            sum0 += __shfl_xor_sync(0xffffffffu, sum0, 2);
            sum1 += __shfl_xor_sync(0xffffffffu, sum1, 1);
            sum1 += __shfl_xor_sync(0xffffffffu, sum1, 2);
            if (qc == 0) {
                atomicAdd(&rs[r], sum0);
                atomicAdd(&rs[r + 8], sum1);
            }
        }
        __syncthreads();

        // O += P @ Bv^T  (K = 128 -> 8 k16 steps)
        #pragma unroll
        for (int ks = 0; ks < 8; ks++) {
            uint32_t a0[4], a1[4], b0[4], b1[4];
            ldsm4(a0, spa + ks * 32);
            ldsm4(a1, spa + 16 * 136 * 2 + ks * 32);
            ldsm4(b0, spb + ks * 32);
            ldsm4(b1, spb + 16 * 136 * 2 + ks * 32);
            mma16(oacc[0][0], a0, b0[0], b0[2]); mma16(oacc[0][1], a0, b0[1], b0[3]);
            mma16(oacc[0][2], a0, b1[0], b1[2]); mma16(oacc[0][3], a0, b1[1], b1[3]);
            mma16(oacc[1][0], a1, b0[0], b0[2]); mma16(oacc[1][1], a1, b0[1], b0[3]);
            mma16(oacc[1][2], a1, b1[0], b1[2]); mma16(oacc[1][3], a1, b1[1], b1[3]);
        }
    }
    __syncthreads();

    #pragma unroll
    for (int mt = 0; mt < 2; mt++)
        #pragma unroll
        for (int nt = 0; nt < 4; nt++) {
            int r = wm * 32 + mt * 16 + qr;
            int col = wn * 32 + nt * 8 + qc * 2;
            float i0 = 1.f / rs[r], i1 = 1.f / rs[r + 8];
            *(half2*)(g_att + (size_t)(t0 + r) * 512 + h * 64 + col) =
                __floats2half2_rn(oacc[mt][nt][0] * i0, oacc[mt][nt][1] * i0);
            *(half2*)(g_att + (size_t)(t0 + r + 8) * 512 + h * 64 + col) =
                __floats2half2_rn(oacc[mt][nt][2] * i1, oacc[mt][nt][3] * i1);
        }
}

extern "C" void kernel_launch(void* const* d_in, const int* in_sizes, int n_in,
                              void* d_out, int out_size) {
    const float* x      = (const float*)d_in[0];
    const float* conv_w = (const float*)d_in[1];
    const float* conv_b = (const float*)d_in[2];
    const float* pat    = (const float*)d_in[3];
    const float* wq     = (const float*)d_in[4];
    const float* wkv    = (const float*)d_in[5];
    const float* wout   = (const float*)d_in[6];
    const float* bout   = (const float*)d_in[7];
    float* out = (float*)d_out;

    const int GEMM_SMEM = (2 * 128 * 40 + 2 * 256 * 40) * 2;               // 61440
    const int ATTN_SMEM = (128 * 72 * 2 + 128 * 136 + 64 * 136) * 2 + 512; // 89600
    cudaFuncSetAttribute(k_gemm, cudaFuncAttributeMaxDynamicSharedMemorySize, GEMM_SMEM);
    cudaFuncSetAttribute(k_attn, cudaFuncAttributeMaxDynamicSharedMemorySize, ATTN_SMEM);

    __half* p_wcat; cudaGetSymbolAddress((void**)&p_wcat, g_wcat);
    __half* p_wq;   cudaGetSymbolAddress((void**)&p_wq, g_wq);
    __half* p_wo;   cudaGetSymbolAddress((void**)&p_wo, g_wo);
    __half* p_xh;   cudaGetSymbolAddress((void**)&p_xh, g_xh);
    __half* p_xln;  cudaGetSymbolAddress((void**)&p_xln, g_xln);
    __half* p_q;    cudaGetSymbolAddress((void**)&p_q, g_q);
    __half* p_att;  cudaGetSymbolAddress((void**)&p_att, g_att);

    k_prep<<<768, 256>>>(conv_w, wq, wout);
    k_prepx<<<8192, 256>>>(x);
    k_patkv<<<64, 256>>>(pat, wkv);
    k_gemm<<<512, 512, GEMM_SMEM>>>(p_xh, p_wcat, x, conv_b, p_xln, 768, 256, 0);
    k_gemm<<<dim3(512, 2), 512, GEMM_SMEM>>>(p_xln, p_wq, nullptr, nullptr, p_q, 256, 512, 1);
    k_attn<<<dim3(512, 8), 256, ATTN_SMEM>>>();
    k_gemm<<<512, 512, GEMM_SMEM>>>(p_att, p_wo, nullptr, bout, out, 512, 256, 2);
}

// round 11
// speedup vs baseline: 2.0992x; 2.0992x over previous
#include <cuda_runtime.h>
#include <cuda_fp16.h>
#include <cstdint>
#include <cstddef>

#define DD 256
#define PP 512
#define TT 65536
#define LSEQ 2048
#define EPSL 1e-5f

__device__ __half g_wcat[DD * 768];
__device__ __half g_wq[512 * DD];
__device__ __half g_wo[DD * 512];
__device__ __half g_xh[(size_t)TT * DD];
__device__ __half g_xln[(size_t)TT * DD];
__device__ __half g_q[(size_t)TT * 512];
__device__ __half g_att[(size_t)TT * 512];
__device__ __half g_k[8 * PP * 64];          // [h][w][d], scaled 1/8
__device__ __half g_vT[8 * 64 * PP];         // [h][d][w]

__device__ __forceinline__ uint32_t s2u(const void* p) {
    uint32_t a;
    asm("{ .reg .u64 t; cvta.to.shared.u64 t, %1; cvt.u32.u64 %0, t; }" : "=r"(a) : "l"(p));
    return a;
}
__device__ __forceinline__ uint32_t pack2(float a, float b) {
    half2 h = __floats2half2_rn(a, b);
    return *reinterpret_cast<uint32_t*>(&h);
}
__device__ __forceinline__ void mma16(float* c, const uint32_t* a, uint32_t b0, uint32_t b1) {
    asm volatile(
        "mma.sync.aligned.m16n8k16.row.col.f32.f16.f16.f32 "
        "{%0,%1,%2,%3}, {%4,%5,%6,%7}, {%8,%9}, {%0,%1,%2,%3};"
        : "+f"(c[0]), "+f"(c[1]), "+f"(c[2]), "+f"(c[3])
        : "r"(a[0]), "r"(a[1]), "r"(a[2]), "r"(a[3]), "r"(b0), "r"(b1));
}
__device__ __forceinline__ void ldsm4(uint32_t* r, uint32_t addr) {
    asm volatile("ldmatrix.sync.aligned.m8n8.x4.shared.b16 {%0,%1,%2,%3}, [%4];"
        : "=r"(r[0]), "=r"(r[1]), "=r"(r[2]), "=r"(r[3]) : "r"(addr));
}
__device__ __forceinline__ void cpa16(uint32_t dst, const __half* src) {
    asm volatile("cp.async.ca.shared.global [%0], [%1], 16;" :: "r"(dst), "l"(src));
}
__device__ __forceinline__ void cpa16p(uint32_t dst, const __half* src, int ok) {
    int sz = ok ? 16 : 0;
    asm volatile("cp.async.ca.shared.global [%0], [%1], 16, %2;" :: "r"(dst), "l"(src), "r"(sz));
}
#define CPCOMMIT() asm volatile("cp.async.commit_group;" ::: "memory")

// ---------- K0: weight prep ----------
__global__ void __launch_bounds__(256) k_prep(const float* __restrict__ conv_w,
                                              const float* __restrict__ wq,
                                              const float* __restrict__ wout) {
    int idx = blockIdx.x * 256 + threadIdx.x;
    if (idx < DD * 768) {
        int o = idx / 768, col = idx % 768;
        g_wcat[idx] = __float2half_rn(conv_w[o * 768 + (col & 255) * 3 + (col >> 8)]);
    }
    if (idx < 512 * DD) g_wq[idx] = __float2half_rn(wq[idx]);
    if (idx < DD * 512) g_wo[idx] = __float2half_rn(wout[idx]);
}

// ---------- K0b: x -> half ----------
__global__ void __launch_bounds__(256) k_prepx(const float* __restrict__ x) {
    size_t i = ((size_t)blockIdx.x * 256 + threadIdx.x) * 8;
    float4 v0 = *(const float4*)(x + i);
    float4 v1 = *(const float4*)(x + i + 4);
    half2 h[4];
    h[0] = __floats2half2_rn(v0.x, v0.y);
    h[1] = __floats2half2_rn(v0.z, v0.w);
    h[2] = __floats2half2_rn(v1.x, v1.y);
    h[3] = __floats2half2_rn(v1.z, v1.w);
    *(uint4*)(g_xh + i) = *(uint4*)h;
}

__device__ __forceinline__ float2 bsum2(float a, float b, float* red) {
    #pragma unroll
    for (int o = 16; o; o >>= 1) {
        a += __shfl_xor_sync(0xffffffffu, a, o);
        b += __shfl_xor_sync(0xffffffffu, b, o);
    }
    __syncthreads();
    if ((threadIdx.x & 31) == 0) {
        red[threadIdx.x >> 5] = a;
        red[(threadIdx.x >> 5) + 8] = b;
    }
    __syncthreads();
    a = 0.f; b = 0.f;
    #pragma unroll
    for (int k = 0; k < 8; k++) { a += red[k]; b += red[k + 8]; }
    return make_float2(a, b);
}

// ---------- K1: pattern double-LN + kv ----------
__global__ void __launch_bounds__(256) k_patkv(const float* __restrict__ pattern,
                                               const float* __restrict__ wkv) {
    __shared__ float sp[8][DD];
    __shared__ float red[16];
    int r0 = blockIdx.x * 8, tid = threadIdx.x;
    for (int r = 0; r < 8; r++) {
        float v = pattern[(size_t)(r0 + r) * DD + tid];
        for (int it = 0; it < 2; it++) {
            float2 s = bsum2(v, v * v, red);
            float mu = s.x * (1.f / DD);
            v = (v - mu) * rsqrtf(s.y * (1.f / DD) - mu * mu + EPSL);
        }
        sp[r][tid] = v;
    }
    __syncthreads();
    for (int m = 0; m < 4; m++) {
        int j = m * 256 + tid;
        float acc[8];
        #pragma unroll
        for (int r = 0; r < 8; r++) acc[r] = 0.f;
        const float* wr = wkv + (size_t)j * DD;
        for (int i = 0; i < DD; i++) {
            float w = wr[i];
            #pragma unroll
            for (int r = 0; r < 8; r++) acc[r] += w * sp[r][i];
        }
        int h = j >> 7, e = j & 127;
        if (e < 64) {
            #pragma unroll
            for (int r = 0; r < 8; r++)
                g_k[((size_t)h * PP + r0 + r) * 64 + e] = __float2half_rn(0.125f * acc[r]);
        } else {
            #pragma unroll
            for (int r = 0; r < 8; r++)
                g_vT[((size_t)h * 64 + e - 64) * PP + r0 + r] = __float2half_rn(acc[r]);
        }
    }
}

// ---------- GEMM prefetch (32-half K-chunk) ----------
__device__ __forceinline__ void gemm_prefetch(const __half* A, const __half* B,
                                              uint32_t as_u, uint32_t bs_u,
                                              int c, int K, int t0, int n0,
                                              int seq0, int mode, int tid) {
    int b = c & 1, kc = c * 32;
    uint32_t ad = as_u + b * 128 * 40 * 2;
    uint32_t bd = bs_u + b * 256 * 40 * 2;
    if (mode == 0) {
        for (int i = tid; i < 512; i += 512) {
            int r = i >> 2, cc = i & 3;
            int t = t0 + r + (kc >> 8) - 2;
            int ok = t >= seq0;
            const __half* s = A + (size_t)(ok ? t : seq0) * 256 + (kc & 255) + cc * 8;
            cpa16p(ad + (r * 40 + cc * 8) * 2, s, ok);
        }
    } else {
        for (int i = tid; i < 512; i += 512) {
            int r = i >> 2, cc = i & 3;
            cpa16(ad + (r * 40 + cc * 8) * 2, A + (size_t)(t0 + r) * K + kc + cc * 8);
        }
    }
    for (int i = tid; i < 1024; i += 512) {
        int r = i >> 2, cc = i & 3;
        cpa16(bd + (r * 40 + cc * 8) * 2, B + (size_t)(n0 + r) * K + kc + cc * 8);
    }
    CPCOMMIT();
}

// ---------- fused fp16 GEMM: C[128 x 256] = A[128,K] @ B[256,K]^T (+ epilogues) ----------
__global__ void __launch_bounds__(512, 1) k_gemm(const __half* __restrict__ A,
                                                 const __half* __restrict__ B,
                                                 const float* __restrict__ x,
                                                 const float* __restrict__ bias,
                                                 void* __restrict__ Cv,
                                                 int K, int ldc, int mode) {
    extern __shared__ __half sm[];
    __half* As = sm;                        // [2][128][40]
    __half* Bs = sm + 2 * 128 * 40;         // [2][256][40]
    __shared__ float sred[128], sqred[128];
    int tid = threadIdx.x, lane = tid & 31, warp = tid >> 5;
    int l16 = lane & 15, lh = lane >> 4;
    int qr = lane >> 2, qc = lane & 3;
    int wm = warp >> 2, wn = warp & 3;
    int t0 = blockIdx.x * 128, n0 = blockIdx.y * 256;
    int seq0 = t0 & ~(LSEQ - 1);
    int NC = K >> 5;

    uint32_t as_u = s2u(As), bs_u = s2u(Bs);
    uint32_t a_frag = as_u + ((wm * 32 + l16) * 40 + lh * 8) * 2;
    uint32_t b_frag = bs_u + ((wn * 64 + l16) * 40 + lh * 8) * 2;

    float cacc[2][8][4];
    #pragma unroll
    for (int mt = 0; mt < 2; mt++)
        #pragma unroll
        for (int nt = 0; nt < 8; nt++)
            #pragma unroll
            for (int i = 0; i < 4; i++) cacc[mt][nt][i] = 0.f;

    gemm_prefetch(A, B, as_u, bs_u, 0, K, t0, n0, seq0, mode, tid);
    for (int c = 0; c < NC; c++) {
        if (c + 1 < NC) {
            gemm_prefetch(A, B, as_u, bs_u, c + 1, K, t0, n0, seq0, mode, tid);
            asm volatile("cp.async.wait_group 1;" ::: "memory");
        } else {
            asm volatile("cp.async.wait_group 0;" ::: "memory");
        }
        __syncthreads();
        int b = c & 1;
        uint32_t af = a_frag + b * 128 * 40 * 2;
        uint32_t bf = b_frag + b * 256 * 40 * 2;
        #pragma unroll
        for (int ks = 0; ks < 2; ks++) {
            uint32_t a0[4], a1[4], bb[4][4];
            ldsm4(a0, af + ks * 32);
            ldsm4(a1, af + 16 * 40 * 2 + ks * 32);
            #pragma unroll
            for (int n2 = 0; n2 < 4; n2++) ldsm4(bb[n2], bf + n2 * 16 * 40 * 2 + ks * 32);
            #pragma unroll
            for (int n2 = 0; n2 < 4; n2++) {
                mma16(cacc[0][n2 * 2],     a0, bb[n2][0], bb[n2][2]);
                mma16(cacc[0][n2 * 2 + 1], a0, bb[n2][1], bb[n2][3]);
                mma16(cacc[1][n2 * 2],     a1, bb[n2][0], bb[n2][2]);
                mma16(cacc[1][n2 * 2 + 1], a1, bb[n2][1], bb[n2][3]);
            }
        }
        __syncthreads();
    }

    if (mode == 1) {
        __half* C = (__half*)Cv;
        #pragma unroll
        for (int mt = 0; mt < 2; mt++)
            #pragma unroll
            for (int nt = 0; nt < 8; nt++) {
                int r = t0 + wm * 32 + mt * 16 + qr;
                int col = n0 + wn * 64 + nt * 8 + qc * 2;
                *(half2*)(C + (size_t)r * ldc + col) =
                    __floats2half2_rn(cacc[mt][nt][0], cacc[mt][nt][1]);
                *(half2*)(C + (size_t)(r + 8) * ldc + col) =
                    __floats2half2_rn(cacc[mt][nt][2], cacc[mt][nt][3]);
            }
        return;
    }

    if (tid < 128) { sred[tid] = 0.f; sqred[tid] = 0.f; }
    __syncthreads();

    float bcol[8][2];
    #pragma unroll
    for (int nt = 0; nt < 8; nt++) {
        float2 b2 = *(const float2*)(bias + wn * 64 + nt * 8 + qc * 2);
        bcol[nt][0] = b2.x; bcol[nt][1] = b2.y;
    }
    float s1[4] = {0.f, 0.f, 0.f, 0.f}, sq[4] = {0.f, 0.f, 0.f, 0.f};
    #pragma unroll
    for (int mt = 0; mt < 2; mt++)
        #pragma unroll
        for (int h2 = 0; h2 < 2; h2++) {
            int rr = mt * 2 + h2;
            int r = wm * 32 + mt * 16 + h2 * 8 + qr;
            #pragma unroll
            for (int nt = 0; nt < 8; nt++) {
                float y0 = cacc[mt][nt][h2 * 2] + bcol[nt][0];
                float y1 = cacc[mt][nt][h2 * 2 + 1] + bcol[nt][1];
                if (mode == 0) {
                    float2 rx = *(const float2*)(x + (size_t)(t0 + r) * 256 +
                                                 wn * 64 + nt * 8 + qc * 2);
                    y0 += rx.x; y1 += rx.y;
                    y0 = y0 > 0.f ? y0 : 0.01f * y0;
                    y1 = y1 > 0.f ? y1 : 0.01f * y1;
                }
                cacc[mt][nt][h2 * 2] = y0;
                cacc[mt][nt][h2 * 2 + 1] = y1;
                s1[rr] += y0 + y1;
                sq[rr] += y0 * y0 + y1 * y1;
            }
        }
    #pragma unroll
    for (int o = 1; o <= 2; o <<= 1)
        #pragma unroll
        for (int rr = 0; rr < 4; rr++) {
            s1[rr] += __shfl_xor_sync(0xffffffffu, s1[rr], o);
            sq[rr] += __shfl_xor_sync(0xffffffffu, sq[rr], o);
        }
    if (qc == 0) {
        #pragma unroll
        for (int rr = 0; rr < 4; rr++) {
            int r = wm * 32 + (rr >> 1) * 16 + (rr & 1) * 8 + qr;
            atomicAdd(&sred[r], s1[rr]);
            atomicAdd(&sqred[r], sq[rr]);
        }
    }
    __syncthreads();
    #pragma unroll
    for (int mt = 0; mt < 2; mt++)
        #pragma unroll
        for (int h2 = 0; h2 < 2; h2++) {
            int r = wm * 32 + mt * 16 + h2 * 8 + qr;
            float mu = sred[r] * (1.f / DD);
            float inv = rsqrtf(sqred[r] * (1.f / DD) - mu * mu + EPSL);
            #pragma unroll
            for (int nt = 0; nt < 8; nt++) {
                int col = wn * 64 + nt * 8 + qc * 2;
                float y0 = (cacc[mt][nt][h2 * 2] - mu) * inv;
                float y1 = (cacc[mt][nt][h2 * 2 + 1] - mu) * inv;
                if (mode == 0) {
                    *(half2*)((__half*)Cv + (size_t)(t0 + r) * ldc + col) =
                        __floats2half2_rn(y0, y1);
                } else {
                    *(float2*)((float*)Cv + (size_t)(t0 + r) * ldc + col) =
                        make_float2(y0, y1);
                }
            }
        }
}

// ---------- attn K/V chunk prefetch (64 patterns) ----------
__device__ __forceinline__ void attn_prefetch(uint32_t bk_u, uint32_t bv_u,
                                              int h, int c, int tid) {
    int b = c & 1;
    uint32_t kd = bk_u + b * 64 * 72 * 2;
    uint32_t vd = bv_u + b * 64 * 72 * 2;
    for (int i = tid; i < 512; i += 256) {
        int r = i >> 3, cc = i & 7;
        cpa16(kd + (r * 72 + cc * 8) * 2,
              g_k + ((size_t)h * PP + c * 64 + r) * 64 + cc * 8);
    }
    for (int i = tid; i < 512; i += 256) {
        int r = i >> 3, cc = i & 7;
        cpa16(vd + (r * 72 + cc * 8) * 2,
              g_vT + ((size_t)h * 64 + r) * PP + c * 64 + cc * 8);
    }
    CPCOMMIT();
}

// ---------- FA2-style attention: P stays in registers ----------
// 256 threads; warp w owns rows [w*16, w*16+16); chunk = 64 patterns.
__global__ void __launch_bounds__(256, 2) k_attn() {
    extern __shared__ __half smh[];
    __half* Aq = smh;                    // [128][72]
    __half* Bk = Aq + 128 * 72;          // [2][64][72]
    __half* Bv = Bk + 2 * 64 * 72;       // [2][64][72]
    int tid = threadIdx.x, lane = tid & 31, warp = tid >> 5;
    int l16 = lane & 15, lh = lane >> 4;
    int qr = lane >> 2, qc = lane & 3;
    int t0 = blockIdx.x * 128, h = blockIdx.y;

    uint32_t bk_u = s2u(Bk), bv_u = s2u(Bv);

    for (int i = tid; i < 1024; i += 256) {
        int r = i >> 3, cc = i & 7;
        *(uint4*)(Aq + r * 72 + cc * 8) =
            *(const uint4*)(g_q + (size_t)(t0 + r) * 512 + h * 64 + cc * 8);
    }
    attn_prefetch(bk_u, bv_u, h, 0, tid);

    uint32_t aq_frag = s2u(Aq) + ((warp * 16 + l16) * 72 + lh * 8) * 2;

    float o[8][4];
    #pragma unroll
    for (int dt = 0; dt < 8; dt++)
        #pragma unroll
        for (int i = 0; i < 4; i++) o[dt][i] = 0.f;
    float rs0 = 0.f, rs1 = 0.f;

    for (int c = 0; c < 8; c++) {
        if (c + 1 < 8) {
            attn_prefetch(bk_u, bv_u, h, c + 1, tid);
            asm volatile("cp.async.wait_group 1;" ::: "memory");
        } else {
            asm volatile("cp.async.wait_group 0;" ::: "memory");
        }
        __syncthreads();
        int b = c & 1;
        uint32_t bkf = bk_u + b * 64 * 72 * 2 + (l16 * 72 + lh * 8) * 2;
        uint32_t bvf = bv_u + b * 64 * 72 * 2 + (l16 * 72 + lh * 8) * 2;

        // S[16 x 64] = q_rows @ k_chunk^T  (K = 64 -> 4 k16 steps)
        float s[8][4];
        #pragma unroll
        for (int nt = 0; nt < 8; nt++)
            #pragma unroll
            for (int i = 0; i < 4; i++) s[nt][i] = 0.f;
        #pragma unroll
        for (int ks = 0; ks < 4; ks++) {
            uint32_t a[4];
            ldsm4(a, aq_frag + ks * 32);
            #pragma unroll
            for (int n2 = 0; n2 < 4; n2++) {
                uint32_t bb[4];
                ldsm4(bb, bkf + n2 * 16 * 72 * 2 + ks * 32);
                mma16(s[n2 * 2],     a, bb[0], bb[2]);
                mma16(s[n2 * 2 + 1], a, bb[1], bb[3]);
            }
        }

        // exp in registers -> pack into PV A-fragments (k = pattern)
        uint32_t pa[4][4];
        #pragma unroll
        for (int j = 0; j < 4; j++) {
            float e00 = __expf(s[2 * j][0]),     e01 = __expf(s[2 * j][1]);
            float e02 = __expf(s[2 * j][2]),     e03 = __expf(s[2 * j][3]);
            float e10 = __expf(s[2 * j + 1][0]), e11 = __expf(s[2 * j + 1][1]);
            float e12 = __expf(s[2 * j + 1][2]), e13 = __expf(s[2 * j + 1][3]);
            rs0 += e00 + e01 + e10 + e11;
            rs1 += e02 + e03 + e12 + e13;
            pa[j][0] = pack2(e00, e01);
            pa[j][1] = pack2(e02, e03);
            pa[j][2] = pack2(e10, e11);
            pa[j][3] = pack2(e12, e13);
        }

        // O[16 x 64] += P @ V  (k = 64 patterns -> 4 k16 steps)
        #pragma unroll
        for (int j = 0; j < 4; j++) {
            #pragma unroll
            for (int d2 = 0; d2 < 4; d2++) {
                uint32_t bb[4];
                ldsm4(bb, bvf + d2 * 16 * 72 * 2 + j * 32);
                mma16(o[d2 * 2],     pa[j], bb[0], bb[2]);
                mma16(o[d2 * 2 + 1], pa[j], bb[1], bb[3]);
            }
        }
        __syncthreads();
    }

    // rowsum reduce over quad (qc lanes), normalize, store
    rs0 += __shfl_xor_sync(0xffffffffu, rs0, 1);
    rs0 += __shfl_xor_sync(0xffffffffu, rs0, 2);
    rs1 += __shfl_xor_sync(0xffffffffu, rs1, 1);
    rs1 += __shfl_xor_sync(0xffffffffu, rs1, 2);
    float i0 = 1.f / rs0, i1 = 1.f / rs1;
    int r0 = t0 + warp * 16 + qr;
    #pragma unroll
    for (int dt = 0; dt < 8; dt++) {
        int col = h * 64 + dt * 8 + qc * 2;
        *(half2*)(g_att + (size_t)r0 * 512 + col) =
            __floats2half2_rn(o[dt][0] * i0, o[dt][1] * i0);
        *(half2*)(g_att + (size_t)(r0 + 8) * 512 + col) =
            __floats2half2_rn(o[dt][2] * i1, o[dt][3] * i1);
    }
}

extern "C" void kernel_launch(void* const* d_in, const int* in_sizes, int n_in,
                              void* d_out, int out_size) {
    const float* x      = (const float*)d_in[0];
    const float* conv_w = (const float*)d_in[1];
    const float* conv_b = (const float*)d_in[2];
    const float* pat    = (const float*)d_in[3];
    const float* wq     = (const float*)d_in[4];
    const float* wkv    = (const float*)d_in[5];
    const float* wout   = (const float*)d_in[6];
    const float* bout   = (const float*)d_in[7];
    float* out = (float*)d_out;

    const int GEMM_SMEM = (2 * 128 * 40 + 2 * 256 * 40) * 2;    // 61440
    const int ATTN_SMEM = (128 * 72 + 4 * 64 * 72) * 2;         // 55296
    cudaFuncSetAttribute(k_gemm, cudaFuncAttributeMaxDynamicSharedMemorySize, GEMM_SMEM);
    cudaFuncSetAttribute(k_attn, cudaFuncAttributeMaxDynamicSharedMemorySize, ATTN_SMEM);

    __half* p_wcat; cudaGetSymbolAddress((void**)&p_wcat, g_wcat);
    __half* p_wq;   cudaGetSymbolAddress((void**)&p_wq, g_wq);
    __half* p_wo;   cudaGetSymbolAddress((void**)&p_wo, g_wo);
    __half* p_xh;   cudaGetSymbolAddress((void**)&p_xh, g_xh);
    __half* p_xln;  cudaGetSymbolAddress((void**)&p_xln, g_xln);
    __half* p_q;    cudaGetSymbolAddress((void**)&p_q, g_q);
    __half* p_att;  cudaGetSymbolAddress((void**)&p_att, g_att);

    k_prep<<<768, 256>>>(conv_w, wq, wout);
    k_prepx<<<8192, 256>>>(x);
    k_patkv<<<64, 256>>>(pat, wkv);
    k_gemm<<<512, 512, GEMM_SMEM>>>(p_xh, p_wcat, x, conv_b, p_xln, 768, 256, 0);
    k_gemm<<<dim3(512, 2), 512, GEMM_SMEM>>>(p_xln, p_wq, nullptr, nullptr, p_q, 256, 512, 1);
    k_attn<<<dim3(512, 8), 256, ATTN_SMEM>>>();
    k_gemm<<<512, 512, GEMM_SMEM>>>(p_att, p_wo, nullptr, bout, out, 512, 256, 2);
}

// round 13
// speedup vs baseline: 2.1418x; 1.0203x over previous
#include <cuda_runtime.h>
#include <cuda_fp16.h>
#include <cstdint>
#include <cstddef>

#define DD 256
#define PP 512
#define TT 65536
#define LSEQ 2048
#define EPSL 1e-5f

__device__ __half g_wcat[DD * 768];
__device__ __half g_wq[512 * DD];
__device__ __half g_wo[DD * 512];
__device__ __half g_xh[(size_t)TT * DD];
__device__ __half g_q[(size_t)TT * 512];
__device__ __half g_att[(size_t)TT * 512];
__device__ __half g_k[8 * PP * 64];          // [h][w][d], scaled 1/8
__device__ __half g_vT[8 * 64 * PP];         // [h][d][w]

__device__ __forceinline__ uint32_t s2u(const void* p) {
    uint32_t a;
    asm("{ .reg .u64 t; cvta.to.shared.u64 t, %1; cvt.u32.u64 %0, t; }" : "=r"(a) : "l"(p));
    return a;
}
__device__ __forceinline__ uint32_t pack2(float a, float b) {
    half2 h = __floats2half2_rn(a, b);
    return *reinterpret_cast<uint32_t*>(&h);
}
__device__ __forceinline__ void mma16(float* c, const uint32_t* a, uint32_t b0, uint32_t b1) {
    asm volatile(
        "mma.sync.aligned.m16n8k16.row.col.f32.f16.f16.f32 "
        "{%0,%1,%2,%3}, {%4,%5,%6,%7}, {%8,%9}, {%0,%1,%2,%3};"
        : "+f"(c[0]), "+f"(c[1]), "+f"(c[2]), "+f"(c[3])
        : "r"(a[0]), "r"(a[1]), "r"(a[2]), "r"(a[3]), "r"(b0), "r"(b1));
}
__device__ __forceinline__ void ldsm4(uint32_t* r, uint32_t addr) {
    asm volatile("ldmatrix.sync.aligned.m8n8.x4.shared.b16 {%0,%1,%2,%3}, [%4];"
        : "=r"(r[0]), "=r"(r[1]), "=r"(r[2]), "=r"(r[3]) : "r"(addr));
}
__device__ __forceinline__ void cpa16(uint32_t dst, const __half* src) {
    asm volatile("cp.async.ca.shared.global [%0], [%1], 16;" :: "r"(dst), "l"(src));
}
__device__ __forceinline__ void cpa16p(uint32_t dst, const __half* src, int ok) {
    int sz = ok ? 16 : 0;
    asm volatile("cp.async.ca.shared.global [%0], [%1], 16, %2;" :: "r"(dst), "l"(src), "r"(sz));
}
#define CPCOMMIT() asm volatile("cp.async.commit_group;" ::: "memory")
#define WAITG(n)   asm volatile("cp.async.wait_group %0;" :: "n"(n) : "memory")
// wait so that buffer for current chunk has landed; rem = chunks still in flight after it
__device__ __forceinline__ void wait_pipe(int rem) {
    if (rem >= 2) { WAITG(2); }
    else if (rem == 1) { WAITG(1); }
    else { WAITG(0); }
}

// ---------- K0: weight prep ----------
__global__ void __launch_bounds__(256) k_prep(const float* __restrict__ conv_w,
                                              const float* __restrict__ wq,
                                              const float* __restrict__ wout) {
    int idx = blockIdx.x * 256 + threadIdx.x;
    if (idx < DD * 768) {
        int o = idx / 768, col = idx % 768;
        g_wcat[idx] = __float2half_rn(conv_w[o * 768 + (col & 255) * 3 + (col >> 8)]);
    }
    if (idx < 512 * DD) g_wq[idx] = __float2half_rn(wq[idx]);
    if (idx < DD * 512) g_wo[idx] = __float2half_rn(wout[idx]);
}

// ---------- K0b: x -> half ----------
__global__ void __launch_bounds__(256) k_prepx(const float* __restrict__ x) {
    size_t i = ((size_t)blockIdx.x * 256 + threadIdx.x) * 8;
    float4 v0 = *(const float4*)(x + i);
    float4 v1 = *(const float4*)(x + i + 4);
    half2 h[4];
    h[0] = __floats2half2_rn(v0.x, v0.y);
    h[1] = __floats2half2_rn(v0.z, v0.w);
    h[2] = __floats2half2_rn(v1.x, v1.y);
    h[3] = __floats2half2_rn(v1.z, v1.w);
    *(uint4*)(g_xh + i) = *(uint4*)h;
}

__device__ __forceinline__ float2 bsum2(float a, float b, float* red) {
    #pragma unroll
    for (int o = 16; o; o >>= 1) {
        a += __shfl_xor_sync(0xffffffffu, a, o);
        b += __shfl_xor_sync(0xffffffffu, b, o);
    }
    __syncthreads();
    if ((threadIdx.x & 31) == 0) {
        red[threadIdx.x >> 5] = a;
        red[(threadIdx.x >> 5) + 8] = b;
    }
    __syncthreads();
    a = 0.f; b = 0.f;
    #pragma unroll
    for (int k = 0; k < 8; k++) { a += red[k]; b += red[k + 8]; }
    return make_float2(a, b);
}

// ---------- K1: pattern double-LN + kv ----------
__global__ void __launch_bounds__(256) k_patkv(const float* __restrict__ pattern,
                                               const float* __restrict__ wkv) {
    __shared__ float sp[8][DD];
    __shared__ float red[16];
    int r0 = blockIdx.x * 8, tid = threadIdx.x;
    for (int r = 0; r < 8; r++) {
        float v = pattern[(size_t)(r0 + r) * DD + tid];
        for (int it = 0; it < 2; it++) {
            float2 s = bsum2(v, v * v, red);
            float mu = s.x * (1.f / DD);
            v = (v - mu) * rsqrtf(s.y * (1.f / DD) - mu * mu + EPSL);
        }
        sp[r][tid] = v;
    }
    __syncthreads();
    for (int m = 0; m < 4; m++) {
        int j = m * 256 + tid;
        float acc[8];
        #pragma unroll
        for (int r = 0; r < 8; r++) acc[r] = 0.f;
        const float* wr = wkv + (size_t)j * DD;
        for (int i = 0; i < DD; i++) {
            float w = wr[i];
            #pragma unroll
            for (int r = 0; r < 8; r++) acc[r] += w * sp[r][i];
        }
        int h = j >> 7, e = j & 127;
        if (e < 64) {
            #pragma unroll
            for (int r = 0; r < 8; r++)
                g_k[((size_t)h * PP + r0 + r) * 64 + e] = __float2half_rn(0.125f * acc[r]);
        } else {
            #pragma unroll
            for (int r = 0; r < 8; r++)
                g_vT[((size_t)h * 64 + e - 64) * PP + r0 + r] = __float2half_rn(acc[r]);
        }
    }
}

// ================= K2: fused conv GEMM + LN + q GEMM =================
__device__ __forceinline__ void cq_pref1(uint32_t as_u, uint32_t bs_u,
                                         int c, int t0, int seq0, int tid) {
    int s = c & 3, kc = c * 32;
    uint32_t ad = as_u + s * 128 * 40 * 2;
    uint32_t bd = bs_u + s * 256 * 40 * 2;
    {
        int r = tid >> 2, cc = tid & 3;
        int t = t0 + r + (kc >> 8) - 2;
        int ok = t >= seq0;
        const __half* sp = g_xh + (size_t)(ok ? t : seq0) * 256 + (kc & 255) + cc * 8;
        cpa16p(ad + (r * 40 + cc * 8) * 2, sp, ok);
    }
    for (int i = tid; i < 1024; i += 512) {
        int r = i >> 2, cc = i & 3;
        cpa16(bd + (r * 40 + cc * 8) * 2, g_wcat + (size_t)r * 768 + kc + cc * 8);
    }
    CPCOMMIT();
}
__device__ __forceinline__ void cq_pref2(uint32_t bs_u, int ny, int c, int tid) {
    int s = c & 3, kc = c * 32;
    uint32_t bd = bs_u + s * 256 * 40 * 2;
    for (int i = tid; i < 1024; i += 512) {
        int r = i >> 2, cc = i & 3;
        cpa16(bd + (r * 40 + cc * 8) * 2, g_wq + (size_t)(ny * 256 + r) * 256 + kc + cc * 8);
    }
    CPCOMMIT();
}

__global__ void __launch_bounds__(512, 1) k_convq(const float* __restrict__ x,
                                                  const float* __restrict__ cbias) {
    extern __shared__ __half sm[];
    __half* As = sm;                          // [4][128][40]
    __half* Bs = sm + 4 * 128 * 40;           // [4][256][40]
    __half* Xs = sm + 4 * 128 * 40 + 4 * 256 * 40;  // [128][264]
    __shared__ float sred[128], sqred[128];
    int tid = threadIdx.x, lane = tid & 31, warp = tid >> 5;
    int l16 = lane & 15, lh = lane >> 4;
    int qr = lane >> 2, qc = lane & 3;
    int wm = warp >> 2, wn = warp & 3;
    int t0 = blockIdx.x * 128;
    int seq0 = t0 & ~(LSEQ - 1);

    uint32_t as_u = s2u(As), bs_u = s2u(Bs), xs_u = s2u(Xs);
    uint32_t a_frag = as_u + ((wm * 32 + l16) * 40 + lh * 8) * 2;
    uint32_t b_frag = bs_u + ((wn * 64 + l16) * 40 + lh * 8) * 2;

    float cacc[2][8][4];
    #pragma unroll
    for (int mt = 0; mt < 2; mt++)
        #pragma unroll
        for (int nt = 0; nt < 8; nt++)
            #pragma unroll
            for (int i = 0; i < 4; i++) cacc[mt][nt][i] = 0.f;

    // ---- phase 1: conv GEMM, K=768 ----
    const int NC1 = 24;
    cq_pref1(as_u, bs_u, 0, t0, seq0, tid);
    cq_pref1(as_u, bs_u, 1, t0, seq0, tid);
    cq_pref1(as_u, bs_u, 2, t0, seq0, tid);
    for (int c = 0; c < NC1; c++) {
        wait_pipe(NC1 - 1 - c);
        __syncthreads();                      // all iter c-1 reads done; buffer c ready
        if (c + 3 < NC1) cq_pref1(as_u, bs_u, c + 3, t0, seq0, tid);
        int s = c & 3;
        uint32_t af = a_frag + s * 128 * 40 * 2;
        uint32_t bf = b_frag + s * 256 * 40 * 2;
        #pragma unroll
        for (int ks = 0; ks < 2; ks++) {
            uint32_t a0[4], a1[4], bb[4][4];
            ldsm4(a0, af + ks * 32);
            ldsm4(a1, af + 16 * 40 * 2 + ks * 32);
            #pragma unroll
            for (int n2 = 0; n2 < 4; n2++) ldsm4(bb[n2], bf + n2 * 16 * 40 * 2 + ks * 32);
            #pragma unroll
            for (int n2 = 0; n2 < 4; n2++) {
                mma16(cacc[0][n2 * 2],     a0, bb[n2][0], bb[n2][2]);
                mma16(cacc[0][n2 * 2 + 1], a0, bb[n2][1], bb[n2][3]);
                mma16(cacc[1][n2 * 2],     a1, bb[n2][0], bb[n2][2]);
                mma16(cacc[1][n2 * 2 + 1], a1, bb[n2][1], bb[n2][3]);
            }
        }
    }

    // ---- epilogue: +bias +residual +leaky +LN -> Xs (half) ----
    if (tid < 128) { sred[tid] = 0.f; sqred[tid] = 0.f; }
    __syncthreads();
    float bcol[8][2];
    #pragma unroll
    for (int nt = 0; nt < 8; nt++) {
        float2 b2 = *(const float2*)(cbias + wn * 64 + nt * 8 + qc * 2);
        bcol[nt][0] = b2.x; bcol[nt][1] = b2.y;
    }
    float s1[4] = {0.f, 0.f, 0.f, 0.f}, sq[4] = {0.f, 0.f, 0.f, 0.f};
    #pragma unroll
    for (int mt = 0; mt < 2; mt++)
        #pragma unroll
        for (int h2 = 0; h2 < 2; h2++) {
            int rr = mt * 2 + h2;
            int r = wm * 32 + mt * 16 + h2 * 8 + qr;
            #pragma unroll
            for (int nt = 0; nt < 8; nt++) {
                float2 rx = *(const float2*)(x + (size_t)(t0 + r) * 256 +
                                             wn * 64 + nt * 8 + qc * 2);
                float y0 = cacc[mt][nt][h2 * 2] + bcol[nt][0] + rx.x;
                float y1 = cacc[mt][nt][h2 * 2 + 1] + bcol[nt][1] + rx.y;
                y0 = y0 > 0.f ? y0 : 0.01f * y0;
                y1 = y1 > 0.f ? y1 : 0.01f * y1;
                cacc[mt][nt][h2 * 2] = y0;
                cacc[mt][nt][h2 * 2 + 1] = y1;
                s1[rr] += y0 + y1;
                sq[rr] += y0 * y0 + y1 * y1;
            }
        }
    #pragma unroll
    for (int o = 1; o <= 2; o <<= 1)
        #pragma unroll
        for (int rr = 0; rr < 4; rr++) {
            s1[rr] += __shfl_xor_sync(0xffffffffu, s1[rr], o);
            sq[rr] += __shfl_xor_sync(0xffffffffu, sq[rr], o);
        }
    if (qc == 0) {
        #pragma unroll
        for (int rr = 0; rr < 4; rr++) {
            int r = wm * 32 + (rr >> 1) * 16 + (rr & 1) * 8 + qr;
            atomicAdd(&sred[r], s1[rr]);
            atomicAdd(&sqred[r], sq[rr]);
        }
    }
    __syncthreads();
    #pragma unroll
    for (int mt = 0; mt < 2; mt++)
        #pragma unroll
        for (int h2 = 0; h2 < 2; h2++) {
            int r = wm * 32 + mt * 16 + h2 * 8 + qr;
            float mu = sred[r] * (1.f / DD);
            float inv = rsqrtf(sqred[r] * (1.f / DD) - mu * mu + EPSL);
            #pragma unroll
            for (int nt = 0; nt < 8; nt++) {
                int col = wn * 64 + nt * 8 + qc * 2;
                *(half2*)(Xs + r * 264 + col) =
                    __floats2half2_rn((cacc[mt][nt][h2 * 2] - mu) * inv,
                                      (cacc[mt][nt][h2 * 2 + 1] - mu) * inv);
            }
        }
    __syncthreads();

    // ---- phase 2: q = Xs @ wq^T, two 256-col halves ----
    uint32_t xa_frag = xs_u + ((wm * 32 + l16) * 264 + lh * 8) * 2;
    for (int ny = 0; ny < 2; ny++) {
        __syncthreads();   // all reads of Bs buffers from previous sub-GEMM done
        #pragma unroll
        for (int mt = 0; mt < 2; mt++)
            #pragma unroll
            for (int nt = 0; nt < 8; nt++)
                #pragma unroll
                for (int i = 0; i < 4; i++) cacc[mt][nt][i] = 0.f;
        cq_pref2(bs_u, ny, 0, tid);
        cq_pref2(bs_u, ny, 1, tid);
        cq_pref2(bs_u, ny, 2, tid);
        for (int c = 0; c < 8; c++) {
            wait_pipe(7 - c);
            __syncthreads();
            if (c + 3 < 8) cq_pref2(bs_u, ny, c + 3, tid);
            int s = c & 3;
            uint32_t bf = b_frag + s * 256 * 40 * 2;
            #pragma unroll
            for (int ks = 0; ks < 2; ks++) {
                uint32_t a0[4], a1[4], bb[4][4];
                ldsm4(a0, xa_frag + c * 64 + ks * 32);
                ldsm4(a1, xa_frag + 16 * 264 * 2 + c * 64 + ks * 32);
                #pragma unroll
                for (int n2 = 0; n2 < 4; n2++) ldsm4(bb[n2], bf + n2 * 16 * 40 * 2 + ks * 32);
                #pragma unroll
                for (int n2 = 0; n2 < 4; n2++) {
                    mma16(cacc[0][n2 * 2],     a0, bb[n2][0], bb[n2][2]);
                    mma16(cacc[0][n2 * 2 + 1], a0, bb[n2][1], bb[n2][3]);
                    mma16(cacc[1][n2 * 2],     a1, bb[n2][0], bb[n2][2]);
                    mma16(cacc[1][n2 * 2 + 1], a1, bb[n2][1], bb[n2][3]);
                }
            }
        }
        #pragma unroll
        for (int mt = 0; mt < 2; mt++)
            #pragma unroll
            for (int nt = 0; nt < 8; nt++) {
                int r = t0 + wm * 32 + mt * 16 + qr;
                int col = ny * 256 + wn * 64 + nt * 8 + qc * 2;
                *(half2*)(g_q + (size_t)r * 512 + col) =
                    __floats2half2_rn(cacc[mt][nt][0], cacc[mt][nt][1]);
                *(half2*)(g_q + (size_t)(r + 8) * 512 + col) =
                    __floats2half2_rn(cacc[mt][nt][2], cacc[mt][nt][3]);
            }
    }
}

// ================= K3: FA2 attention (4-stage K/V) =================
__device__ __forceinline__ void attn_prefetch(uint32_t bk_u, uint32_t bv_u,
                                              int h, int c, int tid) {
    int s = c & 3;
    uint32_t kd = bk_u + s * 64 * 72 * 2;
    uint32_t vd = bv_u + s * 64 * 72 * 2;
    for (int i = tid; i < 512; i += 256) {
        int r = i >> 3, cc = i & 7;
        cpa16(kd + (r * 72 + cc * 8) * 2,
              g_k + ((size_t)h * PP + c * 64 + r) * 64 + cc * 8);
    }
    for (int i = tid; i < 512; i += 256) {
        int r = i >> 3, cc = i & 7;
        cpa16(vd + (r * 72 + cc * 8) * 2,
              g_vT + ((size_t)h * 64 + r) * PP + c * 64 + cc * 8);
    }
    CPCOMMIT();
}

__global__ void __launch_bounds__(256, 2) k_attn() {
    extern __shared__ __half smh[];
    __half* Aq = smh;                    // [128][72]
    __half* Bk = Aq + 128 * 72;          // [4][64][72]
    __half* Bv = Bk + 4 * 64 * 72;       // [4][64][72]
    int tid = threadIdx.x, lane = tid & 31, warp = tid >> 5;
    int l16 = lane & 15, lh = lane >> 4;
    int qr = lane >> 2, qc = lane & 3;
    int t0 = blockIdx.x * 128, h = blockIdx.y;

    uint32_t bk_u = s2u(Bk), bv_u = s2u(Bv);

    for (int i = tid; i < 1024; i += 256) {
        int r = i >> 3, cc = i & 7;
        *(uint4*)(Aq + r * 72 + cc * 8) =
            *(const uint4*)(g_q + (size_t)(t0 + r) * 512 + h * 64 + cc * 8);
    }
    attn_prefetch(bk_u, bv_u, h, 0, tid);
    attn_prefetch(bk_u, bv_u, h, 1, tid);
    attn_prefetch(bk_u, bv_u, h, 2, tid);

    uint32_t aq_frag = s2u(Aq) + ((warp * 16 + l16) * 72 + lh * 8) * 2;

    float o[8][4];
    #pragma unroll
    for (int dt = 0; dt < 8; dt++)
        #pragma unroll
        for (int i = 0; i < 4; i++) o[dt][i] = 0.f;
    float rs0 = 0.f, rs1 = 0.f;

    for (int c = 0; c < 8; c++) {
        wait_pipe(7 - c);
        __syncthreads();
        if (c + 3 < 8) attn_prefetch(bk_u, bv_u, h, c + 3, tid);
        int s4 = c & 3;
        uint32_t bkf = bk_u + s4 * 64 * 72 * 2 + (l16 * 72 + lh * 8) * 2;
        uint32_t bvf = bv_u + s4 * 64 * 72 * 2 + (l16 * 72 + lh * 8) * 2;

        float s[8][4];
        #pragma unroll
        for (int nt = 0; nt < 8; nt++)
            #pragma unroll
            for (int i = 0; i < 4; i++) s[nt][i] = 0.f;
        #pragma unroll
        for (int ks = 0; ks < 4; ks++) {
            uint32_t a[4];
            ldsm4(a, aq_frag + ks * 32);
            #pragma unroll
            for (int n2 = 0; n2 < 4; n2++) {
                uint32_t bb[4];
                ldsm4(bb, bkf + n2 * 16 * 72 * 2 + ks * 32);
                mma16(s[n2 * 2],     a, bb[0], bb[2]);
                mma16(s[n2 * 2 + 1], a, bb[1], bb[3]);
            }
        }

        uint32_t pa[4][4];
        #pragma unroll
        for (int j = 0; j < 4; j++) {
            float e00 = __expf(s[2 * j][0]),     e01 = __expf(s[2 * j][1]);
            float e02 = __expf(s[2 * j][2]),     e03 = __expf(s[2 * j][3]);
            float e10 = __expf(s[2 * j + 1][0]), e11 = __expf(s[2 * j + 1][1]);
            float e12 = __expf(s[2 * j + 1][2]), e13 = __expf(s[2 * j + 1][3]);
            rs0 += e00 + e01 + e10 + e11;
            rs1 += e02 + e03 + e12 + e13;
            pa[j][0] = pack2(e00, e01);
            pa[j][1] = pack2(e02, e03);
            pa[j][2] = pack2(e10, e11);
            pa[j][3] = pack2(e12, e13);
        }

        #pragma unroll
        for (int j = 0; j < 4; j++) {
            #pragma unroll
            for (int d2 = 0; d2 < 4; d2++) {
                uint32_t bb[4];
                ldsm4(bb, bvf + d2 * 16 * 72 * 2 + j * 32);
                mma16(o[d2 * 2],     pa[j], bb[0], bb[2]);
                mma16(o[d2 * 2 + 1], pa[j], bb[1], bb[3]);
            }
        }
    }

    rs0 += __shfl_xor_sync(0xffffffffu, rs0, 1);
    rs0 += __shfl_xor_sync(0xffffffffu, rs0, 2);
    rs1 += __shfl_xor_sync(0xffffffffu, rs1, 1);
    rs1 += __shfl_xor_sync(0xffffffffu, rs1, 2);
    float i0 = 1.f / rs0, i1 = 1.f / rs1;
    int r0 = t0 + warp * 16 + qr;
    #pragma unroll
    for (int dt = 0; dt < 8; dt++) {
        int col = h * 64 + dt * 8 + qc * 2;
        *(half2*)(g_att + (size_t)r0 * 512 + col) =
            __floats2half2_rn(o[dt][0] * i0, o[dt][1] * i0);
        *(half2*)(g_att + (size_t)(r0 + 8) * 512 + col) =
            __floats2half2_rn(o[dt][2] * i1, o[dt][3] * i1);
    }
}

// ================= K4: out GEMM (K=512) + bias + LN, 4-stage =================
__device__ __forceinline__ void out_pref(uint32_t as_u, uint32_t bs_u,
                                         int c, int t0, int tid) {
    int s = c & 3, kc = c * 32;
    uint32_t ad = as_u + s * 128 * 40 * 2;
    uint32_t bd = bs_u + s * 256 * 40 * 2;
    {
        int r = tid >> 2, cc = tid & 3;
        cpa16(ad + (r * 40 + cc * 8) * 2, g_att + (size_t)(t0 + r) * 512 + kc + cc * 8);
    }
    for (int i = tid; i < 1024; i += 512) {
        int r = i >> 2, cc = i & 3;
        cpa16(bd + (r * 40 + cc * 8) * 2, g_wo + (size_t)r * 512 + kc + cc * 8);
    }
    CPCOMMIT();
}

__global__ void __launch_bounds__(512, 1) k_out(const float* __restrict__ bout,
                                                float* __restrict__ out) {
    extern __shared__ __half sm[];
    __half* As = sm;                    // [4][128][40]
    __half* Bs = sm + 4 * 128 * 40;     // [4][256][40]
    __shared__ float sred[128], sqred[128];
    int tid = threadIdx.x, lane = tid & 31, warp = tid >> 5;
    int l16 = lane & 15, lh = lane >> 4;
    int qr = lane >> 2, qc = lane & 3;
    int wm = warp >> 2, wn = warp & 3;
    int t0 = blockIdx.x * 128;

    uint32_t as_u = s2u(As), bs_u = s2u(Bs);
    uint32_t a_frag = as_u + ((wm * 32 + l16) * 40 + lh * 8) * 2;
    uint32_t b_frag = bs_u + ((wn * 64 + l16) * 40 + lh * 8) * 2;

    float cacc[2][8][4];
    #pragma unroll
    for (int mt = 0; mt < 2; mt++)
        #pragma unroll
        for (int nt = 0; nt < 8; nt++)
            #pragma unroll
            for (int i = 0; i < 4; i++) cacc[mt][nt][i] = 0.f;

    const int NC = 16;
    out_pref(as_u, bs_u, 0, t0, tid);
    out_pref(as_u, bs_u, 1, t0, tid);
    out_pref(as_u, bs_u, 2, t0, tid);
    for (int c = 0; c < NC; c++) {
        wait_pipe(NC - 1 - c);
        __syncthreads();
        if (c + 3 < NC) out_pref(as_u, bs_u, c + 3, t0, tid);
        int s = c & 3;
        uint32_t af = a_frag + s * 128 * 40 * 2;
        uint32_t bf = b_frag + s * 256 * 40 * 2;
        #pragma unroll
        for (int ks = 0; ks < 2; ks++) {
            uint32_t a0[4], a1[4], bb[4][4];
            ldsm4(a0, af + ks * 32);
            ldsm4(a1, af + 16 * 40 * 2 + ks * 32);
            #pragma unroll
            for (int n2 = 0; n2 < 4; n2++) ldsm4(bb[n2], bf + n2 * 16 * 40 * 2 + ks * 32);
            #pragma unroll
            for (int n2 = 0; n2 < 4; n2++) {
                mma16(cacc[0][n2 * 2],     a0, bb[n2][0], bb[n2][2]);
                mma16(cacc[0][n2 * 2 + 1], a0, bb[n2][1], bb[n2][3]);
                mma16(cacc[1][n2 * 2],     a1, bb[n2][0], bb[n2][2]);
                mma16(cacc[1][n2 * 2 + 1], a1, bb[n2][1], bb[n2][3]);
            }
        }
    }

    if (tid < 128) { sred[tid] = 0.f; sqred[tid] = 0.f; }
    __syncthreads();
    float bcol[8][2];
    #pragma unroll
    for (int nt = 0; nt < 8; nt++) {
        float2 b2 = *(const float2*)(bout + wn * 64 + nt * 8 + qc * 2);
        bcol[nt][0] = b2.x; bcol[nt][1] = b2.y;
    }
    float s1[4] = {0.f, 0.f, 0.f, 0.f}, sq[4] = {0.f, 0.f, 0.f, 0.f};
    #pragma unroll
    for (int mt = 0; mt < 2; mt++)
        #pragma unroll
        for (int h2 = 0; h2 < 2; h2++) {
            int rr = mt * 2 + h2;
            #pragma unroll
            for (int nt = 0; nt < 8; nt++) {
                float y0 = cacc[mt][nt][h2 * 2] + bcol[nt][0];
                float y1 = cacc[mt][nt][h2 * 2 + 1] + bcol[nt][1];
                cacc[mt][nt][h2 * 2] = y0;
                cacc[mt][nt][h2 * 2 + 1] = y1;
                s1[rr] += y0 + y1;
                sq[rr] += y0 * y0 + y1 * y1;
            }
        }
    #pragma unroll
    for (int o = 1; o <= 2; o <<= 1)
        #pragma unroll
        for (int rr = 0; rr < 4; rr++) {
            s1[rr] += __shfl_xor_sync(0xffffffffu, s1[rr], o);
            sq[rr] += __shfl_xor_sync(0xffffffffu, sq[rr], o);
        }
    if (qc == 0) {
        #pragma unroll
        for (int rr = 0; rr < 4; rr++) {
            int r = wm * 32 + (rr >> 1) * 16 + (rr & 1) * 8 + qr;
            atomicAdd(&sred[r], s1[rr]);
            atomicAdd(&sqred[r], sq[rr]);
        }
    }
    __syncthreads();
    #pragma unroll
    for (int mt = 0; mt < 2; mt++)
        #pragma unroll
        for (int h2 = 0; h2 < 2; h2++) {
            int r = wm * 32 + mt * 16 + h2 * 8 + qr;
            float mu = sred[r] * (1.f / DD);
            float inv = rsqrtf(sqred[r] * (1.f / DD) - mu * mu + EPSL);
            #pragma unroll
            for (int nt = 0; nt < 8; nt++) {
                int col = wn * 64 + nt * 8 + qc * 2;
                *(float2*)(out + (size_t)(t0 + r) * DD + col) =
                    make_float2((cacc[mt][nt][h2 * 2] - mu) * inv,
                                (cacc[mt][nt][h2 * 2 + 1] - mu) * inv);
            }
        }
}

extern "C" void kernel_launch(void* const* d_in, const int* in_sizes, int n_in,
                              void* d_out, int out_size) {
    const float* x      = (const float*)d_in[0];
    const float* conv_w = (const float*)d_in[1];
    const float* conv_b = (const float*)d_in[2];
    const float* pat    = (const float*)d_in[3];
    const float* wq     = (const float*)d_in[4];
    const float* wkv    = (const float*)d_in[5];
    const float* wout   = (const float*)d_in[6];
    const float* bout   = (const float*)d_in[7];
    float* out = (float*)d_out;

    const int CONVQ_SMEM = (4 * 128 * 40 + 4 * 256 * 40 + 128 * 264) * 2;  // 190464
    const int ATTN_SMEM  = (128 * 72 + 8 * 64 * 72) * 2;                   // 92160
    const int OUT_SMEM   = (4 * 128 * 40 + 4 * 256 * 40) * 2;              // 122880
    cudaFuncSetAttribute(k_convq, cudaFuncAttributeMaxDynamicSharedMemorySize, CONVQ_SMEM);
    cudaFuncSetAttribute(k_attn,  cudaFuncAttributeMaxDynamicSharedMemorySize, ATTN_SMEM);
    cudaFuncSetAttribute(k_out,   cudaFuncAttributeMaxDynamicSharedMemorySize, OUT_SMEM);

    k_prep<<<768, 256>>>(conv_w, wq, wout);
    k_prepx<<<8192, 256>>>(x);
    k_patkv<<<64, 256>>>(pat, wkv);
    k_convq<<<512, 512, CONVQ_SMEM>>>(x, conv_b);
    k_attn<<<dim3(512, 8), 256, ATTN_SMEM>>>();
    k_out<<<512, 512, OUT_SMEM>>>(bout, out);
}

// round 14
// speedup vs baseline: 2.1525x; 1.0050x over previous
#include <cuda_runtime.h>
#include <cuda_fp16.h>
#include <cstdint>
#include <cstddef>

#define DD 256
#define PP 512
#define TT 65536
#define LSEQ 2048
#define EPSL 1e-5f

__device__ __half g_wcat[DD * 768];
__device__ __half g_wq[512 * DD];
__device__ __half g_wo[DD * 512];
__device__ __half g_xh[(size_t)TT * DD];
__device__ __half g_q[(size_t)TT * 512];
__device__ __half g_att[(size_t)TT * 512];
__device__ __half g_k[8 * PP * 64];          // [h][w][d], scaled 1/8
__device__ __half g_vT[8 * 64 * PP];         // [h][d][w]

__device__ __forceinline__ uint32_t s2u(const void* p) {
    uint32_t a;
    asm("{ .reg .u64 t; cvta.to.shared.u64 t, %1; cvt.u32.u64 %0, t; }" : "=r"(a) : "l"(p));
    return a;
}
__device__ __forceinline__ uint32_t pack2(float a, float b) {
    half2 h = __floats2half2_rn(a, b);
    return *reinterpret_cast<uint32_t*>(&h);
}
__device__ __forceinline__ void mma16(float* c, const uint32_t* a, uint32_t b0, uint32_t b1) {
    asm volatile(
        "mma.sync.aligned.m16n8k16.row.col.f32.f16.f16.f32 "
        "{%0,%1,%2,%3}, {%4,%5,%6,%7}, {%8,%9}, {%0,%1,%2,%3};"
        : "+f"(c[0]), "+f"(c[1]), "+f"(c[2]), "+f"(c[3])
        : "r"(a[0]), "r"(a[1]), "r"(a[2]), "r"(a[3]), "r"(b0), "r"(b1));
}
__device__ __forceinline__ void ldsm4(uint32_t* r, uint32_t addr) {
    asm volatile("ldmatrix.sync.aligned.m8n8.x4.shared.b16 {%0,%1,%2,%3}, [%4];"
        : "=r"(r[0]), "=r"(r[1]), "=r"(r[2]), "=r"(r[3]) : "r"(addr));
}
__device__ __forceinline__ void cpa16(uint32_t dst, const __half* src) {
    asm volatile("cp.async.ca.shared.global [%0], [%1], 16;" :: "r"(dst), "l"(src));
}
__device__ __forceinline__ void cpa16p(uint32_t dst, const __half* src, int ok) {
    int sz = ok ? 16 : 0;
    asm volatile("cp.async.ca.shared.global [%0], [%1], 16, %2;" :: "r"(dst), "l"(src), "r"(sz));
}
#define CPCOMMIT() asm volatile("cp.async.commit_group;" ::: "memory")
#define WAITG(n)   asm volatile("cp.async.wait_group %0;" :: "n"(n) : "memory")
__device__ __forceinline__ void wait_pipe(int rem) {
    if (rem >= 2) { WAITG(2); }
    else if (rem == 1) { WAITG(1); }
    else { WAITG(0); }
}

// ---------- K0: weight prep ----------
__global__ void __launch_bounds__(256) k_prep(const float* __restrict__ conv_w,
                                              const float* __restrict__ wq,
                                              const float* __restrict__ wout) {
    int idx = blockIdx.x * 256 + threadIdx.x;
    if (idx < DD * 768) {
        int o = idx / 768, col = idx % 768;
        g_wcat[idx] = __float2half_rn(conv_w[o * 768 + (col & 255) * 3 + (col >> 8)]);
    }
    if (idx < 512 * DD) g_wq[idx] = __float2half_rn(wq[idx]);
    if (idx < DD * 512) g_wo[idx] = __float2half_rn(wout[idx]);
}

// ---------- K0b: x -> half ----------
__global__ void __launch_bounds__(256) k_prepx(const float* __restrict__ x) {
    size_t i = ((size_t)blockIdx.x * 256 + threadIdx.x) * 8;
    float4 v0 = *(const float4*)(x + i);
    float4 v1 = *(const float4*)(x + i + 4);
    half2 h[4];
    h[0] = __floats2half2_rn(v0.x, v0.y);
    h[1] = __floats2half2_rn(v0.z, v0.w);
    h[2] = __floats2half2_rn(v1.x, v1.y);
    h[3] = __floats2half2_rn(v1.z, v1.w);
    *(uint4*)(g_xh + i) = *(uint4*)h;
}

__device__ __forceinline__ float2 bsum2(float a, float b, float* red) {
    #pragma unroll
    for (int o = 16; o; o >>= 1) {
        a += __shfl_xor_sync(0xffffffffu, a, o);
        b += __shfl_xor_sync(0xffffffffu, b, o);
    }
    __syncthreads();
    if ((threadIdx.x & 31) == 0) {
        red[threadIdx.x >> 5] = a;
        red[(threadIdx.x >> 5) + 8] = b;
    }
    __syncthreads();
    a = 0.f; b = 0.f;
    #pragma unroll
    for (int k = 0; k < 8; k++) { a += red[k]; b += red[k + 8]; }
    return make_float2(a, b);
}

// ---------- K1: pattern double-LN + kv ----------
__global__ void __launch_bounds__(256) k_patkv(const float* __restrict__ pattern,
                                               const float* __restrict__ wkv) {
    __shared__ float sp[8][DD];
    __shared__ float red[16];
    int r0 = blockIdx.x * 8, tid = threadIdx.x;
    for (int r = 0; r < 8; r++) {
        float v = pattern[(size_t)(r0 + r) * DD + tid];
        for (int it = 0; it < 2; it++) {
            float2 s = bsum2(v, v * v, red);
            float mu = s.x * (1.f / DD);
            v = (v - mu) * rsqrtf(s.y * (1.f / DD) - mu * mu + EPSL);
        }
        sp[r][tid] = v;
    }
    __syncthreads();
    for (int m = 0; m < 4; m++) {
        int j = m * 256 + tid;
        float acc[8];
        #pragma unroll
        for (int r = 0; r < 8; r++) acc[r] = 0.f;
        const float* wr = wkv + (size_t)j * DD;
        for (int i = 0; i < DD; i++) {
            float w = wr[i];
            #pragma unroll
            for (int r = 0; r < 8; r++) acc[r] += w * sp[r][i];
        }
        int h = j >> 7, e = j & 127;
        if (e < 64) {
            #pragma unroll
            for (int r = 0; r < 8; r++)
                g_k[((size_t)h * PP + r0 + r) * 64 + e] = __float2half_rn(0.125f * acc[r]);
        } else {
            #pragma unroll
            for (int r = 0; r < 8; r++)
                g_vT[((size_t)h * 64 + e - 64) * PP + r0 + r] = __float2half_rn(acc[r]);
        }
    }
}

// ================= K2: fused conv GEMM + LN + q GEMM =================
__device__ __forceinline__ void cq_pref1(uint32_t as_u, uint32_t bs_u,
                                         int c, int t0, int seq0, int tid) {
    int s = c & 3, kc = c * 32;
    uint32_t ad = as_u + s * 128 * 40 * 2;
    uint32_t bd = bs_u + s * 256 * 40 * 2;
    {
        int r = tid >> 2, cc = tid & 3;
        int t = t0 + r + (kc >> 8) - 2;
        int ok = t >= seq0;
        const __half* sp = g_xh + (size_t)(ok ? t : seq0) * 256 + (kc & 255) + cc * 8;
        cpa16p(ad + (r * 40 + cc * 8) * 2, sp, ok);
    }
    for (int i = tid; i < 1024; i += 512) {
        int r = i >> 2, cc = i & 3;
        cpa16(bd + (r * 40 + cc * 8) * 2, g_wcat + (size_t)r * 768 + kc + cc * 8);
    }
    CPCOMMIT();
}
__device__ __forceinline__ void cq_pref2(uint32_t bs_u, int ny, int c, int tid) {
    int s = c & 3, kc = c * 32;
    uint32_t bd = bs_u + s * 256 * 40 * 2;
    for (int i = tid; i < 1024; i += 512) {
        int r = i >> 2, cc = i & 3;
        cpa16(bd + (r * 40 + cc * 8) * 2, g_wq + (size_t)(ny * 256 + r) * 256 + kc + cc * 8);
    }
    CPCOMMIT();
}

__global__ void __launch_bounds__(512, 1) k_convq(const float* __restrict__ x,
                                                  const float* __restrict__ cbias) {
    extern __shared__ __half sm[];
    __half* As = sm;                          // [4][128][40]
    __half* Bs = sm + 4 * 128 * 40;           // [4][256][40]
    __half* Xs = sm + 4 * 128 * 40 + 4 * 256 * 40;  // [128][264]
    __shared__ float sred[128], sqred[128];
    int tid = threadIdx.x, lane = tid & 31, warp = tid >> 5;
    int l16 = lane & 15, lh = lane >> 4;
    int qr = lane >> 2, qc = lane & 3;
    int wm = warp >> 2, wn = warp & 3;
    int t0 = blockIdx.x * 128;
    int seq0 = t0 & ~(LSEQ - 1);

    uint32_t as_u = s2u(As), bs_u = s2u(Bs), xs_u = s2u(Xs);
    uint32_t a_frag = as_u + ((wm * 32 + l16) * 40 + lh * 8) * 2;
    uint32_t b_frag = bs_u + ((wn * 64 + l16) * 40 + lh * 8) * 2;

    float cacc[2][8][4];
    #pragma unroll
    for (int mt = 0; mt < 2; mt++)
        #pragma unroll
        for (int nt = 0; nt < 8; nt++)
            #pragma unroll
            for (int i = 0; i < 4; i++) cacc[mt][nt][i] = 0.f;

    const int NC1 = 24;
    cq_pref1(as_u, bs_u, 0, t0, seq0, tid);
    cq_pref1(as_u, bs_u, 1, t0, seq0, tid);
    cq_pref1(as_u, bs_u, 2, t0, seq0, tid);
    for (int c = 0; c < NC1; c++) {
        wait_pipe(NC1 - 1 - c);
        __syncthreads();
        if (c + 3 < NC1) cq_pref1(as_u, bs_u, c + 3, t0, seq0, tid);
        int s = c & 3;
        uint32_t af = a_frag + s * 128 * 40 * 2;
        uint32_t bf = b_frag + s * 256 * 40 * 2;
        #pragma unroll
        for (int ks = 0; ks < 2; ks++) {
            uint32_t a0[4], a1[4], bb[4][4];
            ldsm4(a0, af + ks * 32);
            ldsm4(a1, af + 16 * 40 * 2 + ks * 32);
            #pragma unroll
            for (int n2 = 0; n2 < 4; n2++) ldsm4(bb[n2], bf + n2 * 16 * 40 * 2 + ks * 32);
            #pragma unroll
            for (int n2 = 0; n2 < 4; n2++) {
                mma16(cacc[0][n2 * 2],     a0, bb[n2][0], bb[n2][2]);
                mma16(cacc[0][n2 * 2 + 1], a0, bb[n2][1], bb[n2][3]);
                mma16(cacc[1][n2 * 2],     a1, bb[n2][0], bb[n2][2]);
                mma16(cacc[1][n2 * 2 + 1], a1, bb[n2][1], bb[n2][3]);
            }
        }
    }

    if (tid < 128) { sred[tid] = 0.f; sqred[tid] = 0.f; }
    __syncthreads();
    float bcol[8][2];
    #pragma unroll
    for (int nt = 0; nt < 8; nt++) {
        float2 b2 = *(const float2*)(cbias + wn * 64 + nt * 8 + qc * 2);
        bcol[nt][0] = b2.x; bcol[nt][1] = b2.y;
    }
    float s1[4] = {0.f, 0.f, 0.f, 0.f}, sq[4] = {0.f, 0.f, 0.f, 0.f};
    #pragma unroll
    for (int mt = 0; mt < 2; mt++)
        #pragma unroll
        for (int h2 = 0; h2 < 2; h2++) {
            int rr = mt * 2 + h2;
            int r = wm * 32 + mt * 16 + h2 * 8 + qr;
            #pragma unroll
            for (int nt = 0; nt < 8; nt++) {
                float2 rx = *(const float2*)(x + (size_t)(t0 + r) * 256 +
                                             wn * 64 + nt * 8 + qc * 2);
                float y0 = cacc[mt][nt][h2 * 2] + bcol[nt][0] + rx.x;
                float y1 = cacc[mt][nt][h2 * 2 + 1] + bcol[nt][1] + rx.y;
                y0 = y0 > 0.f ? y0 : 0.01f * y0;
                y1 = y1 > 0.f ? y1 : 0.01f * y1;
                cacc[mt][nt][h2 * 2] = y0;
                cacc[mt][nt][h2 * 2 + 1] = y1;
                s1[rr] += y0 + y1;
                sq[rr] += y0 * y0 + y1 * y1;
            }
        }
    #pragma unroll
    for (int o = 1; o <= 2; o <<= 1)
        #pragma unroll
        for (int rr = 0; rr < 4; rr++) {
            s1[rr] += __shfl_xor_sync(0xffffffffu, s1[rr], o);
            sq[rr] += __shfl_xor_sync(0xffffffffu, sq[rr], o);
        }
    if (qc == 0) {
        #pragma unroll
        for (int rr = 0; rr < 4; rr++) {
            int r = wm * 32 + (rr >> 1) * 16 + (rr & 1) * 8 + qr;
            atomicAdd(&sred[r], s1[rr]);
            atomicAdd(&sqred[r], sq[rr]);
        }
    }
    __syncthreads();
    #pragma unroll
    for (int mt = 0; mt < 2; mt++)
        #pragma unroll
        for (int h2 = 0; h2 < 2; h2++) {
            int r = wm * 32 + mt * 16 + h2 * 8 + qr;
            float mu = sred[r] * (1.f / DD);
            float inv = rsqrtf(sqred[r] * (1.f / DD) - mu * mu + EPSL);
            #pragma unroll
            for (int nt = 0; nt < 8; nt++) {
                int col = wn * 64 + nt * 8 + qc * 2;
                *(half2*)(Xs + r * 264 + col) =
                    __floats2half2_rn((cacc[mt][nt][h2 * 2] - mu) * inv,
                                      (cacc[mt][nt][h2 * 2 + 1] - mu) * inv);
            }
        }
    __syncthreads();

    uint32_t xa_frag = xs_u + ((wm * 32 + l16) * 264 + lh * 8) * 2;
    for (int ny = 0; ny < 2; ny++) {
        __syncthreads();
        #pragma unroll
        for (int mt = 0; mt < 2; mt++)
            #pragma unroll
            for (int nt = 0; nt < 8; nt++)
                #pragma unroll
                for (int i = 0; i < 4; i++) cacc[mt][nt][i] = 0.f;
        cq_pref2(bs_u, ny, 0, tid);
        cq_pref2(bs_u, ny, 1, tid);
        cq_pref2(bs_u, ny, 2, tid);
        for (int c = 0; c < 8; c++) {
            wait_pipe(7 - c);
            __syncthreads();
            if (c + 3 < 8) cq_pref2(bs_u, ny, c + 3, tid);
            int s = c & 3;
            uint32_t bf = b_frag + s * 256 * 40 * 2;
            #pragma unroll
            for (int ks = 0; ks < 2; ks++) {
                uint32_t a0[4], a1[4], bb[4][4];
                ldsm4(a0, xa_frag + c * 64 + ks * 32);
                ldsm4(a1, xa_frag + 16 * 264 * 2 + c * 64 + ks * 32);
                #pragma unroll
                for (int n2 = 0; n2 < 4; n2++) ldsm4(bb[n2], bf + n2 * 16 * 40 * 2 + ks * 32);
                #pragma unroll
                for (int n2 = 0; n2 < 4; n2++) {
                    mma16(cacc[0][n2 * 2],     a0, bb[n2][0], bb[n2][2]);
                    mma16(cacc[0][n2 * 2 + 1], a0, bb[n2][1], bb[n2][3]);
                    mma16(cacc[1][n2 * 2],     a1, bb[n2][0], bb[n2][2]);
                    mma16(cacc[1][n2 * 2 + 1], a1, bb[n2][1], bb[n2][3]);
                }
            }
        }
        #pragma unroll
        for (int mt = 0; mt < 2; mt++)
            #pragma unroll
            for (int nt = 0; nt < 8; nt++) {
                int r = t0 + wm * 32 + mt * 16 + qr;
                int col = ny * 256 + wn * 64 + nt * 8 + qc * 2;
                *(half2*)(g_q + (size_t)r * 512 + col) =
                    __floats2half2_rn(cacc[mt][nt][0], cacc[mt][nt][1]);
                *(half2*)(g_q + (size_t)(r + 8) * 512 + col) =
                    __floats2half2_rn(cacc[mt][nt][2], cacc[mt][nt][3]);
            }
    }
}

// ================= K3: FA2 attention, interleaved pipes =================
__device__ __forceinline__ void attn_prefetch(uint32_t bk_u, uint32_t bv_u,
                                              int h, int c, int tid) {
    int s = c & 3;
    uint32_t kd = bk_u + s * 64 * 72 * 2;
    uint32_t vd = bv_u + s * 64 * 72 * 2;
    for (int i = tid; i < 512; i += 256) {
        int r = i >> 3, cc = i & 7;
        cpa16(kd + (r * 72 + cc * 8) * 2,
              g_k + ((size_t)h * PP + c * 64 + r) * 64 + cc * 8);
    }
    for (int i = tid; i < 512; i += 256) {
        int r = i >> 3, cc = i & 7;
        cpa16(vd + (r * 72 + cc * 8) * 2,
              g_vT + ((size_t)h * 64 + r) * PP + c * 64 + cc * 8);
    }
    CPCOMMIT();
}

__global__ void __launch_bounds__(256, 2) k_attn() {
    extern __shared__ __half smh[];
    __half* Aq = smh;                    // [128][72]
    __half* Bk = Aq + 128 * 72;          // [4][64][72]
    __half* Bv = Bk + 4 * 64 * 72;       // [4][64][72]
    int tid = threadIdx.x, lane = tid & 31, warp = tid >> 5;
    int l16 = lane & 15, lh = lane >> 4;
    int qr = lane >> 2, qc = lane & 3;
    int t0 = blockIdx.x * 128, h = blockIdx.y;

    uint32_t bk_u = s2u(Bk), bv_u = s2u(Bv);

    for (int i = tid; i < 1024; i += 256) {
        int r = i >> 3, cc = i & 7;
        *(uint4*)(Aq + r * 72 + cc * 8) =
            *(const uint4*)(g_q + (size_t)(t0 + r) * 512 + h * 64 + cc * 8);
    }
    attn_prefetch(bk_u, bv_u, h, 0, tid);
    attn_prefetch(bk_u, bv_u, h, 1, tid);
    attn_prefetch(bk_u, bv_u, h, 2, tid);
    __syncthreads();

    // hoist q A-fragments (invariant over chunks)
    uint32_t aq_frag = s2u(Aq) + ((warp * 16 + l16) * 72 + lh * 8) * 2;
    uint32_t aq[4][4];
    #pragma unroll
    for (int ks = 0; ks < 4; ks++) ldsm4(aq[ks], aq_frag + ks * 32);

    float o[8][4];
    #pragma unroll
    for (int dt = 0; dt < 8; dt++)
        #pragma unroll
        for (int i = 0; i < 4; i++) o[dt][i] = 0.f;
    float rs0 = 0.f, rs1 = 0.f;

    for (int c = 0; c < 8; c++) {
        wait_pipe(7 - c);
        __syncthreads();
        if (c + 3 < 8) attn_prefetch(bk_u, bv_u, h, c + 3, tid);
        int s4 = c & 3;
        uint32_t bkf = bk_u + s4 * 64 * 72 * 2 + (l16 * 72 + lh * 8) * 2;
        uint32_t bvf = bv_u + s4 * 64 * 72 * 2 + (l16 * 72 + lh * 8) * 2;

        // per 16-pattern group: S-mma -> exp -> PV-mma (pipes interleaved)
        #pragma unroll
        for (int n2 = 0; n2 < 4; n2++) {
            float s0[4] = {0.f, 0.f, 0.f, 0.f};
            float s1v[4] = {0.f, 0.f, 0.f, 0.f};
            #pragma unroll
            for (int ks = 0; ks < 4; ks++) {
                uint32_t bb[4];
                ldsm4(bb, bkf + n2 * 16 * 72 * 2 + ks * 32);
                mma16(s0, aq[ks], bb[0], bb[2]);
                mma16(s1v, aq[ks], bb[1], bb[3]);
            }
            float e00 = __expf(s0[0]),  e01 = __expf(s0[1]);
            float e02 = __expf(s0[2]),  e03 = __expf(s0[3]);
            float e10 = __expf(s1v[0]), e11 = __expf(s1v[1]);
            float e12 = __expf(s1v[2]), e13 = __expf(s1v[3]);
            rs0 += e00 + e01 + e10 + e11;
            rs1 += e02 + e03 + e12 + e13;
            uint32_t pa[4];
            pa[0] = pack2(e00, e01);
            pa[1] = pack2(e02, e03);
            pa[2] = pack2(e10, e11);
            pa[3] = pack2(e12, e13);
            #pragma unroll
            for (int d2 = 0; d2 < 4; d2++) {
                uint32_t bb[4];
                ldsm4(bb, bvf + d2 * 16 * 72 * 2 + n2 * 32);
                mma16(o[d2 * 2],     pa, bb[0], bb[2]);
                mma16(o[d2 * 2 + 1], pa, bb[1], bb[3]);
            }
        }
    }

    rs0 += __shfl_xor_sync(0xffffffffu, rs0, 1);
    rs0 += __shfl_xor_sync(0xffffffffu, rs0, 2);
    rs1 += __shfl_xor_sync(0xffffffffu, rs1, 1);
    rs1 += __shfl_xor_sync(0xffffffffu, rs1, 2);
    float i0 = 1.f / rs0, i1 = 1.f / rs1;
    int r0 = t0 + warp * 16 + qr;
    #pragma unroll
    for (int dt = 0; dt < 8; dt++) {
        int col = h * 64 + dt * 8 + qc * 2;
        *(half2*)(g_att + (size_t)r0 * 512 + col) =
            __floats2half2_rn(o[dt][0] * i0, o[dt][1] * i0);
        *(half2*)(g_att + (size_t)(r0 + 8) * 512 + col) =
            __floats2half2_rn(o[dt][2] * i1, o[dt][3] * i1);
    }
}

// ================= K4: out GEMM (K=512) + bias + LN =================
__device__ __forceinline__ void out_pref(uint32_t as_u, uint32_t bs_u,
                                         int c, int t0, int tid) {
    int s = c & 3, kc = c * 32;
    uint32_t ad = as_u + s * 128 * 40 * 2;
    uint32_t bd = bs_u + s * 256 * 40 * 2;
    {
        int r = tid >> 2, cc = tid & 3;
        cpa16(ad + (r * 40 + cc * 8) * 2, g_att + (size_t)(t0 + r) * 512 + kc + cc * 8);
    }
    for (int i = tid; i < 1024; i += 512) {
        int r = i >> 2, cc = i & 3;
        cpa16(bd + (r * 40 + cc * 8) * 2, g_wo + (size_t)r * 512 + kc + cc * 8);
    }
    CPCOMMIT();
}

__global__ void __launch_bounds__(512, 1) k_out(const float* __restrict__ bout,
                                                float* __restrict__ out) {
    extern __shared__ __half sm[];
    __half* As = sm;
    __half* Bs = sm + 4 * 128 * 40;
    __shared__ float sred[128], sqred[128];
    int tid = threadIdx.x, lane = tid & 31, warp = tid >> 5;
    int l16 = lane & 15, lh = lane >> 4;
    int qr = lane >> 2, qc = lane & 3;
    int wm = warp >> 2, wn = warp & 3;
    int t0 = blockIdx.x * 128;

    uint32_t as_u = s2u(As), bs_u = s2u(Bs);
    uint32_t a_frag = as_u + ((wm * 32 + l16) * 40 + lh * 8) * 2;
    uint32_t b_frag = bs_u + ((wn * 64 + l16) * 40 + lh * 8) * 2;

    float cacc[2][8][4];
    #pragma unroll
    for (int mt = 0; mt < 2; mt++)
        #pragma unroll
        for (int nt = 0; nt < 8; nt++)
            #pragma unroll
            for (int i = 0; i < 4; i++) cacc[mt][nt][i] = 0.f;

    const int NC = 16;
    out_pref(as_u, bs_u, 0, t0, tid);
    out_pref(as_u, bs_u, 1, t0, tid);
    out_pref(as_u, bs_u, 2, t0, tid);
    for (int c = 0; c < NC; c++) {
        wait_pipe(NC - 1 - c);
        __syncthreads();
        if (c + 3 < NC) out_pref(as_u, bs_u, c + 3, t0, tid);
        int s = c & 3;
        uint32_t af = a_frag + s * 128 * 40 * 2;
        uint32_t bf = b_frag + s * 256 * 40 * 2;
        #pragma unroll
        for (int ks = 0; ks < 2; ks++) {
            uint32_t a0[4], a1[4], bb[4][4];
            ldsm4(a0, af + ks * 32);
            ldsm4(a1, af + 16 * 40 * 2 + ks * 32);
            #pragma unroll
            for (int n2 = 0; n2 < 4; n2++) ldsm4(bb[n2], bf + n2 * 16 * 40 * 2 + ks * 32);
            #pragma unroll
            for (int n2 = 0; n2 < 4; n2++) {
                mma16(cacc[0][n2 * 2],     a0, bb[n2][0], bb[n2][2]);
                mma16(cacc[0][n2 * 2 + 1], a0, bb[n2][1], bb[n2][3]);
                mma16(cacc[1][n2 * 2],     a1, bb[n2][0], bb[n2][2]);
                mma16(cacc[1][n2 * 2 + 1], a1, bb[n2][1], bb[n2][3]);
            }
        }
    }

    if (tid < 128) { sred[tid] = 0.f; sqred[tid] = 0.f; }
    __syncthreads();
    float bcol[8][2];
    #pragma unroll
    for (int nt = 0; nt < 8; nt++) {
        float2 b2 = *(const float2*)(bout + wn * 64 + nt * 8 + qc * 2);
        bcol[nt][0] = b2.x; bcol[nt][1] = b2.y;
    }
    float s1[4] = {0.f, 0.f, 0.f, 0.f}, sq[4] = {0.f, 0.f, 0.f, 0.f};
    #pragma unroll
    for (int mt = 0; mt < 2; mt++)
        #pragma unroll
        for (int h2 = 0; h2 < 2; h2++) {
            int rr = mt * 2 + h2;
            #pragma unroll
            for (int nt = 0; nt < 8; nt++) {
                float y0 = cacc[mt][nt][h2 * 2] + bcol[nt][0];
                float y1 = cacc[mt][nt][h2 * 2 + 1] + bcol[nt][1];
                cacc[mt][nt][h2 * 2] = y0;
                cacc[mt][nt][h2 * 2 + 1] = y1;
                s1[rr] += y0 + y1;
                sq[rr] += y0 * y0 + y1 * y1;
            }
        }
    #pragma unroll
    for (int o = 1; o <= 2; o <<= 1)
        #pragma unroll
        for (int rr = 0; rr < 4; rr++) {
            s1[rr] += __shfl_xor_sync(0xffffffffu, s1[rr], o);
            sq[rr] += __shfl_xor_sync(0xffffffffu, sq[rr], o);
        }
    if (qc == 0) {
        #pragma unroll
        for (int rr = 0; rr < 4; rr++) {
            int r = wm * 32 + (rr >> 1) * 16 + (rr & 1) * 8 + qr;
            atomicAdd(&sred[r], s1[rr]);
            atomicAdd(&sqred[r], sq[rr]);
        }
    }
    __syncthreads();
    #pragma unroll
    for (int mt = 0; mt < 2; mt++)
        #pragma unroll
        for (int h2 = 0; h2 < 2; h2++) {
            int r = wm * 32 + mt * 16 + h2 * 8 + qr;
            float mu = sred[r] * (1.f / DD);
            float inv = rsqrtf(sqred[r] * (1.f / DD) - mu * mu + EPSL);
            #pragma unroll
            for (int nt = 0; nt < 8; nt++) {
                int col = wn * 64 + nt * 8 + qc * 2;
                *(float2*)(out + (size_t)(t0 + r) * DD + col) =
                    make_float2((cacc[mt][nt][h2 * 2] - mu) * inv,
                                (cacc[mt][nt][h2 * 2 + 1] - mu) * inv);
            }
        }
}

extern "C" void kernel_launch(void* const* d_in, const int* in_sizes, int n_in,
                              void* d_out, int out_size) {
    const float* x      = (const float*)d_in[0];
    const float* conv_w = (const float*)d_in[1];
    const float* conv_b = (const float*)d_in[2];
    const float* pat    = (const float*)d_in[3];
    const float* wq     = (const float*)d_in[4];
    const float* wkv    = (const float*)d_in[5];
    const float* wout   = (const float*)d_in[6];
    const float* bout   = (const float*)d_in[7];
    float* out = (float*)d_out;

    const int CONVQ_SMEM = (4 * 128 * 40 + 4 * 256 * 40 + 128 * 264) * 2;  // 190464
    const int ATTN_SMEM  = (128 * 72 + 8 * 64 * 72) * 2;                   // 92160
    const int OUT_SMEM   = (4 * 128 * 40 + 4 * 256 * 40) * 2;              // 122880
    cudaFuncSetAttribute(k_convq, cudaFuncAttributeMaxDynamicSharedMemorySize, CONVQ_SMEM);
    cudaFuncSetAttribute(k_attn,  cudaFuncAttributeMaxDynamicSharedMemorySize, ATTN_SMEM);
    cudaFuncSetAttribute(k_out,   cudaFuncAttributeMaxDynamicSharedMemorySize, OUT_SMEM);

    k_prep<<<768, 256>>>(conv_w, wq, wout);
    k_prepx<<<8192, 256>>>(x);
    k_patkv<<<64, 256>>>(pat, wkv);
    k_convq<<<512, 512, CONVQ_SMEM>>>(x, conv_b);
    k_attn<<<dim3(512, 8), 256, ATTN_SMEM>>>();
    k_out<<<512, 512, OUT_SMEM>>>(bout, out);
}

// round 15
// speedup vs baseline: 2.1531x; 1.0003x over previous
#include <cuda_runtime.h>
#include <cuda_fp16.h>
#include <cstdint>
#include <cstddef>

#define DD 256
#define PP 512
#define TT 65536
#define LSEQ 2048
#define EPSL 1e-5f

__device__ __half g_wcat[DD * 768];
__device__ __half g_wq[512 * DD];
__device__ __half g_wo[DD * 512];
__device__ __half g_xh[(size_t)TT * DD];
__device__ __half g_xln[(size_t)TT * DD];
__device__ __half g_q[(size_t)TT * 512];
__device__ __half g_att[(size_t)TT * 512];
__device__ __half g_k[8 * PP * 64];          // [h][w][d], scaled 1/8
__device__ __half g_vT[8 * 64 * PP];         // [h][d][w]

__device__ __forceinline__ uint32_t s2u(const void* p) {
    uint32_t a;
    asm("{ .reg .u64 t; cvta.to.shared.u64 t, %1; cvt.u32.u64 %0, t; }" : "=r"(a) : "l"(p));
    return a;
}
__device__ __forceinline__ uint32_t pack2(float a, float b) {
    half2 h = __floats2half2_rn(a, b);
    return *reinterpret_cast<uint32_t*>(&h);
}
__device__ __forceinline__ void mma16(float* c, const uint32_t* a, uint32_t b0, uint32_t b1) {
    asm volatile(
        "mma.sync.aligned.m16n8k16.row.col.f32.f16.f16.f32 "
        "{%0,%1,%2,%3}, {%4,%5,%6,%7}, {%8,%9}, {%0,%1,%2,%3};"
        : "+f"(c[0]), "+f"(c[1]), "+f"(c[2]), "+f"(c[3])
        : "r"(a[0]), "r"(a[1]), "r"(a[2]), "r"(a[3]), "r"(b0), "r"(b1));
}
__device__ __forceinline__ void ldsm4(uint32_t* r, uint32_t addr) {
    asm volatile("ldmatrix.sync.aligned.m8n8.x4.shared.b16 {%0,%1,%2,%3}, [%4];"
        : "=r"(r[0]), "=r"(r[1]), "=r"(r[2]), "=r"(r[3]) : "r"(addr));
}
__device__ __forceinline__ void cpa16(uint32_t dst, const __half* src) {
    asm volatile("cp.async.ca.shared.global [%0], [%1], 16;" :: "r"(dst), "l"(src));
}
__device__ __forceinline__ void cpa16p(uint32_t dst, const __half* src, int ok) {
    int sz = ok ? 16 : 0;
    asm volatile("cp.async.ca.shared.global [%0], [%1], 16, %2;" :: "r"(dst), "l"(src), "r"(sz));
}
#define CPCOMMIT() asm volatile("cp.async.commit_group;" ::: "memory")
#define WAITG(n)   asm volatile("cp.async.wait_group %0;" :: "n"(n) : "memory")
__device__ __forceinline__ void wait_pipe(int rem) {
    if (rem >= 2) { WAITG(2); }
    else if (rem == 1) { WAITG(1); }
    else { WAITG(0); }
}

// ---------- K0: weight prep ----------
__global__ void __launch_bounds__(256) k_prep(const float* __restrict__ conv_w,
                                              const float* __restrict__ wq,
                                              const float* __restrict__ wout) {
    int idx = blockIdx.x * 256 + threadIdx.x;
    if (idx < DD * 768) {
        int o = idx / 768, col = idx % 768;
        g_wcat[idx] = __float2half_rn(conv_w[o * 768 + (col & 255) * 3 + (col >> 8)]);
    }
    if (idx < 512 * DD) g_wq[idx] = __float2half_rn(wq[idx]);
    if (idx < DD * 512) g_wo[idx] = __float2half_rn(wout[idx]);
}

// ---------- K0b: x -> half ----------
__global__ void __launch_bounds__(256) k_prepx(const float* __restrict__ x) {
    size_t i = ((size_t)blockIdx.x * 256 + threadIdx.x) * 8;
    float4 v0 = *(const float4*)(x + i);
    float4 v1 = *(const float4*)(x + i + 4);
    half2 h[4];
    h[0] = __floats2half2_rn(v0.x, v0.y);
    h[1] = __floats2half2_rn(v0.z, v0.w);
    h[2] = __floats2half2_rn(v1.x, v1.y);
    h[3] = __floats2half2_rn(v1.z, v1.w);
    *(uint4*)(g_xh + i) = *(uint4*)h;
}

__device__ __forceinline__ float2 bsum2(float a, float b, float* red) {
    #pragma unroll
    for (int o = 16; o; o >>= 1) {
        a += __shfl_xor_sync(0xffffffffu, a, o);
        b += __shfl_xor_sync(0xffffffffu, b, o);
    }
    __syncthreads();
    if ((threadIdx.x & 31) == 0) {
        red[threadIdx.x >> 5] = a;
        red[(threadIdx.x >> 5) + 8] = b;
    }
    __syncthreads();
    a = 0.f; b = 0.f;
    #pragma unroll
    for (int k = 0; k < 8; k++) { a += red[k]; b += red[k + 8]; }
    return make_float2(a, b);
}

// ---------- K1: pattern double-LN + kv ----------
__global__ void __launch_bounds__(256) k_patkv(const float* __restrict__ pattern,
                                               const float* __restrict__ wkv) {
    __shared__ float sp[8][DD];
    __shared__ float red[16];
    int r0 = blockIdx.x * 8, tid = threadIdx.x;
    for (int r = 0; r < 8; r++) {
        float v = pattern[(size_t)(r0 + r) * DD + tid];
        for (int it = 0; it < 2; it++) {
            float2 s = bsum2(v, v * v, red);
            float mu = s.x * (1.f / DD);
            v = (v - mu) * rsqrtf(s.y * (1.f / DD) - mu * mu + EPSL);
        }
        sp[r][tid] = v;
    }
    __syncthreads();
    for (int m = 0; m < 4; m++) {
        int j = m * 256 + tid;
        float acc[8];
        #pragma unroll
        for (int r = 0; r < 8; r++) acc[r] = 0.f;
        const float* wr = wkv + (size_t)j * DD;
        for (int i = 0; i < DD; i++) {
            float w = wr[i];
            #pragma unroll
            for (int r = 0; r < 8; r++) acc[r] += w * sp[r][i];
        }
        int h = j >> 7, e = j & 127;
        if (e < 64) {
            #pragma unroll
            for (int r = 0; r < 8; r++)
                g_k[((size_t)h * PP + r0 + r) * 64 + e] = __float2half_rn(0.125f * acc[r]);
        } else {
            #pragma unroll
            for (int r = 0; r < 8; r++)
                g_vT[((size_t)h * 64 + e - 64) * PP + r0 + r] = __float2half_rn(acc[r]);
        }
    }
}

// ================= generic 64x256 GEMM, 256 threads, 3-stage, 2 CTA/SM =================
// mode 0: conv (A=g_xh taps/mask, +cbias +x residual +leaky +LN -> g_xln half)
// mode 1: q    (A=g_xln, plain -> g_q half, col offset n0)
// mode 2: out  (A=g_att, +bout +LN -> out float)
__device__ __forceinline__ void g_pref(const __half* A, const __half* B,
                                       uint32_t as_u, uint32_t bs_u,
                                       int c, int K, int t0, int n0,
                                       int seq0, int mode, int tid) {
    int s = c % 3, kc = c * 32;
    uint32_t ad = as_u + s * 64 * 40 * 2;
    uint32_t bd = bs_u + s * 256 * 40 * 2;
    {
        int r = tid >> 2, cc = tid & 3;   // 64 rows x 4 segs = 256 threads
        if (mode == 0) {
            int t = t0 + r + (kc >> 8) - 2;
            int ok = t >= seq0;
            const __half* sp = A + (size_t)(ok ? t : seq0) * 256 + (kc & 255) + cc * 8;
            cpa16p(ad + (r * 40 + cc * 8) * 2, sp, ok);
        } else {
            cpa16(ad + (r * 40 + cc * 8) * 2, A + (size_t)(t0 + r) * K + kc + cc * 8);
        }
    }
    for (int i = tid; i < 1024; i += 256) {
        int r = i >> 2, cc = i & 3;
        cpa16(bd + (r * 40 + cc * 8) * 2, B + (size_t)(n0 + r) * K + kc + cc * 8);
    }
    CPCOMMIT();
}

__global__ void __launch_bounds__(256, 2) k_gemm(const __half* __restrict__ A,
                                                 const __half* __restrict__ B,
                                                 const float* __restrict__ x,
                                                 const float* __restrict__ bias,
                                                 void* __restrict__ Cv,
                                                 int K, int ldc, int mode) {
    extern __shared__ __half sm[];
    __half* As = sm;                    // [3][64][40]
    __half* Bs = sm + 3 * 64 * 40;      // [3][256][40]
    __shared__ float sred[64], sqred[64];
    int tid = threadIdx.x, lane = tid & 31, warp = tid >> 5;
    int l16 = lane & 15, lh = lane >> 4;
    int qr = lane >> 2, qc = lane & 3;
    int wm = warp >> 2, wn = warp & 3;       // 2 x 4 warps, warp tile 32x64
    int t0 = blockIdx.x * 64, n0 = blockIdx.y * 256;
    int seq0 = t0 & ~(LSEQ - 1);
    int NC = K >> 5;

    uint32_t as_u = s2u(As), bs_u = s2u(Bs);
    uint32_t a_frag = as_u + ((wm * 32 + l16) * 40 + lh * 8) * 2;
    uint32_t b_frag = bs_u + ((wn * 64 + l16) * 40 + lh * 8) * 2;

    float cacc[2][8][4];
    #pragma unroll
    for (int mt = 0; mt < 2; mt++)
        #pragma unroll
        for (int nt = 0; nt < 8; nt++)
            #pragma unroll
            for (int i = 0; i < 4; i++) cacc[mt][nt][i] = 0.f;

    g_pref(A, B, as_u, bs_u, 0, K, t0, n0, seq0, mode, tid);
    g_pref(A, B, as_u, bs_u, 1, K, t0, n0, seq0, mode, tid);
    for (int c = 0; c < NC; c++) {
        if (c + 1 < NC) { WAITG(1); } else { WAITG(0); }
        __syncthreads();
        if (c + 2 < NC) g_pref(A, B, as_u, bs_u, c + 2, K, t0, n0, seq0, mode, tid);
        int s = c % 3;
        uint32_t af = a_frag + s * 64 * 40 * 2;
        uint32_t bf = b_frag + s * 256 * 40 * 2;
        #pragma unroll
        for (int ks = 0; ks < 2; ks++) {
            uint32_t a0[4], a1[4], bb[4][4];
            ldsm4(a0, af + ks * 32);
            ldsm4(a1, af + 16 * 40 * 2 + ks * 32);
            #pragma unroll
            for (int n2 = 0; n2 < 4; n2++) ldsm4(bb[n2], bf + n2 * 16 * 40 * 2 + ks * 32);
            #pragma unroll
            for (int n2 = 0; n2 < 4; n2++) {
                mma16(cacc[0][n2 * 2],     a0, bb[n2][0], bb[n2][2]);
                mma16(cacc[0][n2 * 2 + 1], a0, bb[n2][1], bb[n2][3]);
                mma16(cacc[1][n2 * 2],     a1, bb[n2][0], bb[n2][2]);
                mma16(cacc[1][n2 * 2 + 1], a1, bb[n2][1], bb[n2][3]);
            }
        }
    }

    if (mode == 1) {
        __half* C = (__half*)Cv;
        #pragma unroll
        for (int mt = 0; mt < 2; mt++)
            #pragma unroll
            for (int nt = 0; nt < 8; nt++) {
                int r = t0 + wm * 32 + mt * 16 + qr;
                int col = n0 + wn * 64 + nt * 8 + qc * 2;
                *(half2*)(C + (size_t)r * ldc + col) =
                    __floats2half2_rn(cacc[mt][nt][0], cacc[mt][nt][1]);
                *(half2*)(C + (size_t)(r + 8) * ldc + col) =
                    __floats2half2_rn(cacc[mt][nt][2], cacc[mt][nt][3]);
            }
        return;
    }

    // fused bias (+residual/leaky) + LN epilogue over full 256-wide rows
    if (tid < 64) { sred[tid] = 0.f; sqred[tid] = 0.f; }
    __syncthreads();
    float bcol[8][2];
    #pragma unroll
    for (int nt = 0; nt < 8; nt++) {
        float2 b2 = *(const float2*)(bias + wn * 64 + nt * 8 + qc * 2);
        bcol[nt][0] = b2.x; bcol[nt][1] = b2.y;
    }
    float s1[4] = {0.f, 0.f, 0.f, 0.f}, sq[4] = {0.f, 0.f, 0.f, 0.f};
    #pragma unroll
    for (int mt = 0; mt < 2; mt++)
        #pragma unroll
        for (int h2 = 0; h2 < 2; h2++) {
            int rr = mt * 2 + h2;
            int r = wm * 32 + mt * 16 + h2 * 8 + qr;
            #pragma unroll
            for (int nt = 0; nt < 8; nt++) {
                float y0 = cacc[mt][nt][h2 * 2] + bcol[nt][0];
                float y1 = cacc[mt][nt][h2 * 2 + 1] + bcol[nt][1];
                if (mode == 0) {
                    float2 rx = *(const float2*)(x + (size_t)(t0 + r) * 256 +
                                                 wn * 64 + nt * 8 + qc * 2);
                    y0 += rx.x; y1 += rx.y;
                    y0 = y0 > 0.f ? y0 : 0.01f * y0;
                    y1 = y1 > 0.f ? y1 : 0.01f * y1;
                }
                cacc[mt][nt][h2 * 2] = y0;
                cacc[mt][nt][h2 * 2 + 1] = y1;
                s1[rr] += y0 + y1;
                sq[rr] += y0 * y0 + y1 * y1;
            }
        }
    #pragma unroll
    for (int o = 1; o <= 2; o <<= 1)
        #pragma unroll
        for (int rr = 0; rr < 4; rr++) {
            s1[rr] += __shfl_xor_sync(0xffffffffu, s1[rr], o);
            sq[rr] += __shfl_xor_sync(0xffffffffu, sq[rr], o);
        }
    if (qc == 0) {
        #pragma unroll
        for (int rr = 0; rr < 4; rr++) {
            int r = wm * 32 + (rr >> 1) * 16 + (rr & 1) * 8 + qr;
            atomicAdd(&sred[r], s1[rr]);
            atomicAdd(&sqred[r], sq[rr]);
        }
    }
    __syncthreads();
    #pragma unroll
    for (int mt = 0; mt < 2; mt++)
        #pragma unroll
        for (int h2 = 0; h2 < 2; h2++) {
            int r = wm * 32 + mt * 16 + h2 * 8 + qr;
            float mu = sred[r] * (1.f / DD);
            float inv = rsqrtf(sqred[r] * (1.f / DD) - mu * mu + EPSL);
            #pragma unroll
            for (int nt = 0; nt < 8; nt++) {
                int col = wn * 64 + nt * 8 + qc * 2;
                float y0 = (cacc[mt][nt][h2 * 2] - mu) * inv;
                float y1 = (cacc[mt][nt][h2 * 2 + 1] - mu) * inv;
                if (mode == 0) {
                    *(half2*)((__half*)Cv + (size_t)(t0 + r) * ldc + col) =
                        __floats2half2_rn(y0, y1);
                } else {
                    *(float2*)((float*)Cv + (size_t)(t0 + r) * ldc + col) =
                        make_float2(y0, y1);
                }
            }
        }
}

// ================= K3: FA2 attention (unchanged) =================
__device__ __forceinline__ void attn_prefetch(uint32_t bk_u, uint32_t bv_u,
                                              int h, int c, int tid) {
    int s = c & 3;
    uint32_t kd = bk_u + s * 64 * 72 * 2;
    uint32_t vd = bv_u + s * 64 * 72 * 2;
    for (int i = tid; i < 512; i += 256) {
        int r = i >> 3, cc = i & 7;
        cpa16(kd + (r * 72 + cc * 8) * 2,
              g_k + ((size_t)h * PP + c * 64 + r) * 64 + cc * 8);
    }
    for (int i = tid; i < 512; i += 256) {
        int r = i >> 3, cc = i & 7;
        cpa16(vd + (r * 72 + cc * 8) * 2,
              g_vT + ((size_t)h * 64 + r) * PP + c * 64 + cc * 8);
    }
    CPCOMMIT();
}

__global__ void __launch_bounds__(256, 2) k_attn() {
    extern __shared__ __half smh[];
    __half* Aq = smh;                    // [128][72]
    __half* Bk = Aq + 128 * 72;          // [4][64][72]
    __half* Bv = Bk + 4 * 64 * 72;       // [4][64][72]
    int tid = threadIdx.x, lane = tid & 31, warp = tid >> 5;
    int l16 = lane & 15, lh = lane >> 4;
    int qr = lane >> 2, qc = lane & 3;
    int t0 = blockIdx.x * 128, h = blockIdx.y;

    uint32_t bk_u = s2u(Bk), bv_u = s2u(Bv);

    for (int i = tid; i < 1024; i += 256) {
        int r = i >> 3, cc = i & 7;
        *(uint4*)(Aq + r * 72 + cc * 8) =
            *(const uint4*)(g_q + (size_t)(t0 + r) * 512 + h * 64 + cc * 8);
    }
    attn_prefetch(bk_u, bv_u, h, 0, tid);
    attn_prefetch(bk_u, bv_u, h, 1, tid);
    attn_prefetch(bk_u, bv_u, h, 2, tid);
    __syncthreads();

    uint32_t aq_frag = s2u(Aq) + ((warp * 16 + l16) * 72 + lh * 8) * 2;
    uint32_t aq[4][4];
    #pragma unroll
    for (int ks = 0; ks < 4; ks++) ldsm4(aq[ks], aq_frag + ks * 32);

    float o[8][4];
    #pragma unroll
    for (int dt = 0; dt < 8; dt++)
        #pragma unroll
        for (int i = 0; i < 4; i++) o[dt][i] = 0.f;
    float rs0 = 0.f, rs1 = 0.f;

    for (int c = 0; c < 8; c++) {
        wait_pipe(7 - c);
        __syncthreads();
        if (c + 3 < 8) attn_prefetch(bk_u, bv_u, h, c + 3, tid);
        int s4 = c & 3;
        uint32_t bkf = bk_u + s4 * 64 * 72 * 2 + (l16 * 72 + lh * 8) * 2;
        uint32_t bvf = bv_u + s4 * 64 * 72 * 2 + (l16 * 72 + lh * 8) * 2;

        #pragma unroll
        for (int n2 = 0; n2 < 4; n2++) {
            float s0[4] = {0.f, 0.f, 0.f, 0.f};
            float s1v[4] = {0.f, 0.f, 0.f, 0.f};
            #pragma unroll
            for (int ks = 0; ks < 4; ks++) {
                uint32_t bb[4];
                ldsm4(bb, bkf + n2 * 16 * 72 * 2 + ks * 32);
                mma16(s0, aq[ks], bb[0], bb[2]);
                mma16(s1v, aq[ks], bb[1], bb[3]);
            }
            float e00 = __expf(s0[0]),  e01 = __expf(s0[1]);
            float e02 = __expf(s0[2]),  e03 = __expf(s0[3]);
            float e10 = __expf(s1v[0]), e11 = __expf(s1v[1]);
            float e12 = __expf(s1v[2]), e13 = __expf(s1v[3]);
            rs0 += e00 + e01 + e10 + e11;
            rs1 += e02 + e03 + e12 + e13;
            uint32_t pa[4];
            pa[0] = pack2(e00, e01);
            pa[1] = pack2(e02, e03);
            pa[2] = pack2(e10, e11);
            pa[3] = pack2(e12, e13);
            #pragma unroll
            for (int d2 = 0; d2 < 4; d2++) {
                uint32_t bb[4];
                ldsm4(bb, bvf + d2 * 16 * 72 * 2 + n2 * 32);
                mma16(o[d2 * 2],     pa, bb[0], bb[2]);
                mma16(o[d2 * 2 + 1], pa, bb[1], bb[3]);
            }
        }
    }

    rs0 += __shfl_xor_sync(0xffffffffu, rs0, 1);
    rs0 += __shfl_xor_sync(0xffffffffu, rs0, 2);
    rs1 += __shfl_xor_sync(0xffffffffu, rs1, 1);
    rs1 += __shfl_xor_sync(0xffffffffu, rs1, 2);
    float i0 = 1.f / rs0, i1 = 1.f / rs1;
    int r0 = t0 + warp * 16 + qr;
    #pragma unroll
    for (int dt = 0; dt < 8; dt++) {
        int col = h * 64 + dt * 8 + qc * 2;
        *(half2*)(g_att + (size_t)r0 * 512 + col) =
            __floats2half2_rn(o[dt][0] * i0, o[dt][1] * i0);
        *(half2*)(g_att + (size_t)(r0 + 8) * 512 + col) =
            __floats2half2_rn(o[dt][2] * i1, o[dt][3] * i1);
    }
}

extern "C" void kernel_launch(void* const* d_in, const int* in_sizes, int n_in,
                              void* d_out, int out_size) {
    const float* x      = (const float*)d_in[0];
    const float* conv_w = (const float*)d_in[1];
    const float* conv_b = (const float*)d_in[2];
    const float* pat    = (const float*)d_in[3];
    const float* wq     = (const float*)d_in[4];
    const float* wkv    = (const float*)d_in[5];
    const float* wout   = (const float*)d_in[6];
    const float* bout   = (const float*)d_in[7];
    float* out = (float*)d_out;

    const int GEMM_SMEM = (3 * 64 * 40 + 3 * 256 * 40) * 2;   // 76800
    const int ATTN_SMEM = (128 * 72 + 8 * 64 * 72) * 2;       // 92160
    cudaFuncSetAttribute(k_gemm, cudaFuncAttributeMaxDynamicSharedMemorySize, GEMM_SMEM);
    cudaFuncSetAttribute(k_attn, cudaFuncAttributeMaxDynamicSharedMemorySize, ATTN_SMEM);

    __half* p_wcat; cudaGetSymbolAddress((void**)&p_wcat, g_wcat);
    __half* p_wq;   cudaGetSymbolAddress((void**)&p_wq, g_wq);
    __half* p_wo;   cudaGetSymbolAddress((void**)&p_wo, g_wo);
    __half* p_xh;   cudaGetSymbolAddress((void**)&p_xh, g_xh);
    __half* p_xln;  cudaGetSymbolAddress((void**)&p_xln, g_xln);
    __half* p_q;    cudaGetSymbolAddress((void**)&p_q, g_q);
    __half* p_att;  cudaGetSymbolAddress((void**)&p_att, g_att);

    k_prep<<<768, 256>>>(conv_w, wq, wout);
    k_prepx<<<8192, 256>>>(x);
    k_patkv<<<64, 256>>>(pat, wkv);
    // conv: fused bias+res+leaky+LN -> g_xln
    k_gemm<<<1024, 256, GEMM_SMEM>>>(p_xh, p_wcat, x, conv_b, p_xln, 768, 256, 0);
    // q: plain
    k_gemm<<<dim3(1024, 2), 256, GEMM_SMEM>>>(p_xln, p_wq, nullptr, nullptr, p_q, 256, 512, 1);
    k_attn<<<dim3(512, 8), 256, ATTN_SMEM>>>();
    // out: fused bias+LN -> out
    k_gemm<<<1024, 256, GEMM_SMEM>>>(p_att, p_wo, nullptr, bout, out, 512, 256, 2);
}